// round 8
// baseline (speedup 1.0000x reference)
#include <cuda_runtime.h>
#include <math.h>

#define N_NODES 4096
#define H 256
#define E_EDGES 131072

typedef unsigned long long u64;

__device__ __forceinline__ void ffma2(u64 &d, u64 a, u64 b) {
    asm("fma.rn.f32x2 %0, %1, %2, %0;" : "+l"(d) : "l"(a), "l"(b));
}
__device__ __forceinline__ void mul2(u64 &d, u64 a) {
    asm("mul.rn.f32x2 %0, %0, %1;" : "+l"(d) : "l"(a));
}
__device__ __forceinline__ u64 bcast2(float x) {
    u64 r; asm("mov.b64 %0, {%1, %1};" : "=l"(r) : "f"(x)); return r;
}
__device__ __forceinline__ float2 unpk(u64 v) {
    float2 r; asm("mov.b64 {%0, %1}, %2;" : "=f"(r.x), "=f"(r.y) : "l"(v)); return r;
}

// ---------------- scratch ----------------
__device__ float g_h[N_NODES*H];
__device__ float g_agg[N_NODES*H];
__device__ float g_tmp[N_NODES*H];
__device__ float g_ca[N_NODES*H];
__device__ float g_cb[N_NODES*H];
__device__ float g_qkv[N_NODES*6*H];
__device__ float g_qkt[8*128*N_NODES];   // [qk*4+head][d][n]
__device__ float g_attn[N_NODES*2*H];
__device__ float g_o[N_NODES*2*H];
__device__ float g_o2[N_NODES*2*H];
__device__ int   g_cnt[N_NODES];
__device__ int   g_fillp[N_NODES];
__device__ int   g_off[N_NODES+1];
__device__ int   g_csrs[E_EDGES];
__device__ float g_degf[N_NODES];

// ---------------- CSR build ----------------
__global__ void k_zero() {
    int i = blockIdx.x*256 + threadIdx.x;
    if (i < N_NODES) { g_cnt[i] = 0; g_fillp[i] = 0; }
}
__global__ void k_count(const int* __restrict__ dst) {
    int e = blockIdx.x*256 + threadIdx.x;
    if (e < E_EDGES) atomicAdd(&g_cnt[dst[e]], 1);
}
__global__ void k_scan() {
    __shared__ int ps[1024];
    int t = threadIdx.x;
    int c[4]; int s = 0;
    #pragma unroll
    for (int l = 0; l < 4; l++) { c[l] = g_cnt[t*4+l]; s += c[l]; }
    ps[t] = s;
    __syncthreads();
    for (int d = 1; d < 1024; d <<= 1) {
        int v = (t >= d) ? ps[t-d] : 0;
        __syncthreads();
        ps[t] += v;
        __syncthreads();
    }
    int base = ps[t] - s;
    #pragma unroll
    for (int l = 0; l < 4; l++) {
        g_off[t*4+l] = base;
        base += c[l];
        g_degf[t*4+l] = (float)max(c[l], 1);
    }
    if (t == 1023) g_off[N_NODES] = ps[1023];
}
__global__ void k_fill(const int* __restrict__ src, const int* __restrict__ dst) {
    int e = blockIdx.x*256 + threadIdx.x;
    if (e < E_EDGES) {
        int d = dst[e];
        int p = atomicAdd(&g_fillp[d], 1);
        g_csrs[g_off[d] + p] = src[e];
    }
}

// ---------------- Q/K transpose ----------------
__global__ __launch_bounds__(256) void k_qkT(const float* __restrict__ qkv,
                                             float* __restrict__ qkt) {
    __shared__ float tile[32][33];
    int nt = blockIdx.x*32;
    int dt = blockIdx.y*32;
    int g  = dt >> 7;
    int cb = (g >> 2)*512 + (g & 3)*128 + (dt & 127);
    int tx = threadIdx.x & 31, ty = threadIdx.x >> 5;
    #pragma unroll
    for (int i = 0; i < 4; i++)
        tile[ty + i*8][tx] = qkv[(size_t)(nt + ty + i*8)*1536 + cb + tx];
    __syncthreads();
    #pragma unroll
    for (int i = 0; i < 4; i++)
        qkt[(size_t)(dt + ty + i*8)*N_NODES + nt + tx] = tile[tx][ty + i*8];
}

// ---------------- mean aggregation ----------------
__global__ __launch_bounds__(256) void k_agg(const float* __restrict__ h,
                                             float* __restrict__ agg) {
    int n = blockIdx.x;
    int f = threadIdx.x;
    int s = g_off[n], e = g_off[n+1];
    __shared__ int nb[256];
    float acc = 0.f;
    for (int base = s; base < e; base += 256) {
        int m = min(256, e - base);
        if (f < m) nb[f] = g_csrs[base + f];
        __syncthreads();
        for (int j = 0; j < m; j++)
            acc += h[(size_t)nb[j]*H + f];
        __syncthreads();
    }
    agg[(size_t)n*H + f] = acc / g_degf[n];
}

// ---------------- segmented SGEMM (f32x2, A-dup, double-buffered) ----------------
// C[M,Ncols] = [A0|A1|A2] * [B0;B1;B2]^T + bias.  256-wide K segments.
// Per-segment A: pointer, row stride, row shift.  Per-segment B: pointer (row
// stride ldb, element stride es shared).
#define BM 64
#define BN 128
#define BK 16
#define ADS 132   // As dup row stride
#define BST 132

__global__ __launch_bounds__(256) void k_sgemm(
    const float* __restrict__ A0, int ld0, int sh0,
    const float* __restrict__ A1, int ld1, int sh1,
    const float* __restrict__ A2, int ld2, int sh2,
    const float* __restrict__ B0, const float* __restrict__ B1,
    const float* __restrict__ B2, int ldb, int es,
    float* __restrict__ C, int ldc,
    int M, int K, int Ncols,
    const float* __restrict__ bias)
{
    __shared__ float As[2][BK*ADS];
    __shared__ float Bs[2][BK*BST];
    int bm = blockIdx.y * BM;
    int bn = blockIdx.x * BN;
    int t  = threadIdx.x;
    int mg = t >> 4, ng = t & 15;
    int m0  = mg*4;
    int n0a = ng*4;
    int n0b = 64 + ng*4;

    // per-thread load coords
    int la_r = t >> 4, la_k = t & 15;          // A: 4 rows per thread (stride 16... no: flat)
    // A: 64 rows x 16 k = 1024 elems, 4 per thread: flat = t + l*256
    // B: 128 rows x 16 k = 2048 elems, 8 per thread

    u64 acc2[4][4];
    #pragma unroll
    for (int m = 0; m < 4; m++)
        #pragma unroll
        for (int j = 0; j < 4; j++) acc2[m][j] = 0ULL;

    // ---- prologue: load tile k0=0 directly ----
    {
        const float* A = A0; int lda = ld0, sh = sh0;
        #pragma unroll
        for (int l = 0; l < 4; l++) {
            int flat = t + l*256;
            int ar = flat >> 4, ak = flat & 15;
            int gr = bm + ar + sh;
            float a = (gr >= 0 && gr < M) ? A[(size_t)gr*lda + ak] : 0.f;
            *(float2*)&As[0][ak*ADS + 2*ar] = make_float2(a, a);
        }
        #pragma unroll
        for (int l = 0; l < 8; l++) {
            int flat = t + l*256;
            int br = flat >> 4, bk = flat & 15;
            int gc = bn + br;
            Bs[0][bk*BST + br] = (gc < Ncols) ? B0[(size_t)gc*ldb + bk*es] : 0.f;
        }
    }
    __syncthreads();

    int buf = 0;
    for (int k0 = 0; k0 < K; k0 += BK) {
        int nk = k0 + BK;
        float ra[4]; float rb[8];
        if (nk < K) {
            int seg = nk >> 8;
            const float* A = (seg == 0) ? A0 : (seg == 1) ? A1 : A2;
            int lda = (seg == 0) ? ld0 : (seg == 1) ? ld1 : ld2;
            int sh  = (seg == 0) ? sh0 : (seg == 1) ? sh1 : sh2;
            const float* B = (seg == 0) ? B0 : (seg == 1) ? B1 : B2;
            int kc = nk & 255;
            #pragma unroll
            for (int l = 0; l < 4; l++) {
                int flat = t + l*256;
                int ar = flat >> 4, ak = flat & 15;
                int gr = bm + ar + sh;
                ra[l] = (gr >= 0 && gr < M) ? A[(size_t)gr*lda + kc + ak] : 0.f;
            }
            #pragma unroll
            for (int l = 0; l < 8; l++) {
                int flat = t + l*256;
                int br = flat >> 4, bk = flat & 15;
                int gc = bn + br;
                rb[l] = (gc < Ncols) ? B[(size_t)gc*ldb + (kc + bk)*es] : 0.f;
            }
        }
        // ---- compute current buffer ----
        #pragma unroll
        for (int kk = 0; kk < BK; kk++) {
            ulonglong2 ad0 = *(const ulonglong2*)&As[buf][kk*ADS + 2*m0];
            ulonglong2 ad1 = *(const ulonglong2*)&As[buf][kk*ADS + 2*m0 + 4];
            ulonglong2 bA  = *(const ulonglong2*)&Bs[buf][kk*BST + n0a];
            ulonglong2 bB  = *(const ulonglong2*)&Bs[buf][kk*BST + n0b];
            u64 ap[4] = {ad0.x, ad0.y, ad1.x, ad1.y};
            u64 bp[4] = {bA.x, bA.y, bB.x, bB.y};
            #pragma unroll
            for (int m = 0; m < 4; m++) {
                ffma2(acc2[m][0], ap[m], bp[0]);
                ffma2(acc2[m][1], ap[m], bp[1]);
                ffma2(acc2[m][2], ap[m], bp[2]);
                ffma2(acc2[m][3], ap[m], bp[3]);
            }
        }
        if (nk < K) {
            int nb2 = buf ^ 1;
            #pragma unroll
            for (int l = 0; l < 4; l++) {
                int flat = t + l*256;
                int ar = flat >> 4, ak = flat & 15;
                *(float2*)&As[nb2][ak*ADS + 2*ar] = make_float2(ra[l], ra[l]);
            }
            #pragma unroll
            for (int l = 0; l < 8; l++) {
                int flat = t + l*256;
                int br = flat >> 4, bk = flat & 15;
                Bs[nb2][bk*BST + br] = rb[l];
            }
        }
        __syncthreads();
        buf ^= 1;
    }

    int ca = bn + n0a, cb = bn + n0b;
    float4 bsa = make_float4(0.f,0.f,0.f,0.f), bsb = bsa;
    if (ca < Ncols) bsa = *(const float4*)&bias[ca];
    if (cb < Ncols) bsb = *(const float4*)&bias[cb];
    #pragma unroll
    for (int m = 0; m < 4; m++) {
        int row = bm + m0 + m;
        float2 u0 = unpk(acc2[m][0]), u1 = unpk(acc2[m][1]);
        float2 u2 = unpk(acc2[m][2]), u3 = unpk(acc2[m][3]);
        if (ca < Ncols)
            *(float4*)&C[(size_t)row*ldc + ca] =
                make_float4(u0.x+bsa.x, u0.y+bsa.y, u1.x+bsa.z, u1.y+bsa.w);
        if (cb < Ncols)
            *(float4*)&C[(size_t)row*ldc + cb] =
                make_float4(u2.x+bsb.x, u2.y+bsb.y, u3.x+bsb.z, u3.y+bsb.w);
    }
}

// ---------------- LayerNorm / activation ----------------
#define F_LN       1
#define F_POSTRELU 2
#define F_RES      4
#define F_PRERELU  8

__global__ __launch_bounds__(256) void k_ln(
    const float* __restrict__ x, const float* __restrict__ g, const float* __restrict__ b,
    const float* __restrict__ res, float* __restrict__ out, int W, int flags)
{
    __shared__ float rs[8], rq[8];
    __shared__ float s_mean, s_rstd;
    int row = blockIdx.x, t = threadIdx.x;
    const float* xr = x + (size_t)row*W;
    int two = (W == 512);
    float v0 = xr[t];
    float v1 = two ? xr[t + 256] : 0.f;
    if (flags & F_PRERELU) { v0 = fmaxf(v0, 0.f); v1 = fmaxf(v1, 0.f); }
    float s = v0 + v1, sq = v0*v0 + v1*v1;
    #pragma unroll
    for (int o = 16; o > 0; o >>= 1) {
        s  += __shfl_xor_sync(0xffffffff, s,  o);
        sq += __shfl_xor_sync(0xffffffff, sq, o);
    }
    int warp = t >> 5, lane = t & 31;
    if (lane == 0) { rs[warp] = s; rq[warp] = sq; }
    __syncthreads();
    if (t == 0) {
        float S = 0.f, Q = 0.f;
        #pragma unroll
        for (int w = 0; w < 8; w++) { S += rs[w]; Q += rq[w]; }
        float mean = S / (float)W;
        float var = fmaxf(Q / (float)W - mean*mean, 0.f);
        s_mean = mean;
        s_rstd = rsqrtf(var + 1e-5f);
    }
    __syncthreads();
    float mean = s_mean, rstd = s_rstd;

    float val = v0;
    if (flags & F_LN)       val = (val - mean)*rstd*g[t] + b[t];
    if (flags & F_POSTRELU) val = fmaxf(val, 0.f);
    if (flags & F_RES)      val += res[(size_t)row*W + t];
    out[(size_t)row*W + t] = val;

    if (two) {
        int c = t + 256;
        float val2 = v1;
        if (flags & F_LN)       val2 = (val2 - mean)*rstd*g[c] + b[c];
        if (flags & F_POSTRELU) val2 = fmaxf(val2, 0.f);
        if (flags & F_RES)      val2 += res[(size_t)row*W + c];
        out[(size_t)row*W + c] = val2;
    }
}

// ---------------- flash attention (f32x2, occ 2, reg-prefetch) ----------------
// BQ=64, BKV=32, 256 threads.
// Qt  [128 d][68]: transposed Q, natural q-pairs.
// Kdup[128 d][68]: k dup pairs (k,k) — QK pairs over q, zero MOVs.
// Vs  [32 n][132]: V rows.
// Sdup[64 q][68]:  S dup pairs over k for PV.
#define QTS 68
#define KDS 68
#define VSS 132
#define SDS 68
#define OFF_KD (128*QTS)
#define OFF_V  (OFF_KD + 128*KDS)
#define OFF_S  (OFF_V + 32*VSS)
#define OFF_R  (OFF_S + 64*SDS)
#define FLASH_SMEM ((OFF_R + 192)*4)

__global__ __launch_bounds__(256, 2) void k_flash(const float* __restrict__ qkv,
                                                  const float* __restrict__ qkt,
                                                  float* __restrict__ outp)
{
    extern __shared__ float sm[];
    float* Qt   = sm;
    float* Kdup = sm + OFF_KD;
    float* Vs   = sm + OFF_V;
    float* Sdup = sm + OFF_S;
    float* rowm = sm + OFF_R;
    float* rowl = rowm + 64;
    float* rowf = rowl + 64;

    int qb = blockIdx.x, head = blockIdx.y, t = threadIdx.x;
    int n0 = qb*64, coff = head*128;
    int qg = t >> 4, kg = t & 15;
    int q0 = qg*4;
    int pd0 = 4*kg, pd1 = 64 + 4*kg;

    const float* Qg = qkt + (size_t)head*128*N_NODES + n0;
    const float* Kg = qkt + (size_t)(4 + head)*128*N_NODES;

    // ---- load Q transposed tile: Qt[d][q] ----
    #pragma unroll
    for (int l = 0; l < 8; l++) {
        int f4 = t + l*256;
        int r = f4 >> 4, c = f4 & 15;
        *(float4*)&Qt[r*QTS + 4*c] = *(const float4*)&Qg[(size_t)r*N_NODES + 4*c];
    }
    // ---- prologue: load K/V tile kb=0 ----
    #pragma unroll
    for (int l = 0; l < 4; l++) {
        int f4 = t + l*256;
        int r = f4 >> 3, c = f4 & 7;
        float4 v = *(const float4*)&Kg[(size_t)r*N_NODES + 4*c];
        *(float4*)&Kdup[r*KDS + 8*c]     = make_float4(v.x, v.x, v.y, v.y);
        *(float4*)&Kdup[r*KDS + 8*c + 4] = make_float4(v.z, v.z, v.w, v.w);
    }
    #pragma unroll
    for (int l = 0; l < 4; l++) {
        int f4 = t + l*256;
        int r = f4 >> 5, c = f4 & 31;
        *(float4*)&Vs[r*VSS + 4*c] =
            *(const float4*)&qkv[(size_t)r*1536 + 1024 + coff + 4*c];
    }
    if (t < 64) { rowm[t] = -1e30f; rowl[t] = 0.f; }
    __syncthreads();

    u64 oacc[4][4];
    #pragma unroll
    for (int i = 0; i < 4; i++)
        #pragma unroll
        for (int c = 0; c < 4; c++) oacc[i][c] = 0ULL;

    const float scale = 0.08838834764831845f;  // 1/sqrt(128)

    for (int kb = 0; kb < 128; kb++) {
        // ---- prefetch next K/V tile into registers ----
        int kb1 = kb + 1;
        float4 kreg[4], vreg[4];
        if (kb1 < 128) {
            #pragma unroll
            for (int l = 0; l < 4; l++) {
                int f4 = t + l*256;
                int r = f4 >> 3, c = f4 & 7;
                kreg[l] = *(const float4*)&Kg[(size_t)r*N_NODES + kb1*32 + 4*c];
            }
            #pragma unroll
            for (int l = 0; l < 4; l++) {
                int f4 = t + l*256;
                int r = f4 >> 5, c = f4 & 31;
                vreg[l] = *(const float4*)&qkv[(size_t)(kb1*32 + r)*1536 + 1024 + coff + 4*c];
            }
        }
        // ---- S = Q K^T : pairs over q, k dup-broadcast ----
        u64 sacc[2][2] = {{0ULL,0ULL},{0ULL,0ULL}};
        #pragma unroll 4
        for (int d = 0; d < 128; d++) {
            ulonglong2 qp = *(const ulonglong2*)&Qt[d*QTS + q0];
            ulonglong2 kd = *(const ulonglong2*)&Kdup[d*KDS + 4*kg];
            ffma2(sacc[0][0], qp.x, kd.x); ffma2(sacc[0][1], qp.x, kd.y);
            ffma2(sacc[1][0], qp.y, kd.x); ffma2(sacc[1][1], qp.y, kd.y);
        }
        // rows q0+0,q0+1 from sacc[0] (q-pair), q0+2,q0+3 from sacc[1]
        #pragma unroll
        for (int p = 0; p < 2; p++) {
            float2 uk0 = unpk(sacc[p][0]);   // (q_even*k0, q_odd*k0)
            float2 uk1 = unpk(sacc[p][1]);   // (q_even*k1, q_odd*k1)
            *(float4*)&Sdup[(q0 + 2*p    )*SDS + 4*kg] =
                make_float4(uk0.x*scale, uk0.x*scale, uk1.x*scale, uk1.x*scale);
            *(float4*)&Sdup[(q0 + 2*p + 1)*SDS + 4*kg] =
                make_float4(uk0.y*scale, uk0.y*scale, uk1.y*scale, uk1.y*scale);
        }
        __syncthreads();
        // ---- online softmax: 4 threads/row, 8 k (16 dup floats) each ----
        {
            int sr = t >> 2, cc = (t & 3)*16;
            float4 v[4];
            float mold = rowm[sr];
            float mx = mold;
            #pragma unroll
            for (int j = 0; j < 4; j++) {
                v[j] = *(float4*)&Sdup[sr*SDS + cc + 4*j];
                mx = fmaxf(mx, fmaxf(v[j].x, v[j].z));
            }
            mx = fmaxf(mx, __shfl_xor_sync(0xffffffffu, mx, 1));
            mx = fmaxf(mx, __shfl_xor_sync(0xffffffffu, mx, 2));
            float ls = 0.f;
            #pragma unroll
            for (int j = 0; j < 4; j++) {
                float e0 = __expf(v[j].x - mx);
                float e1 = __expf(v[j].z - mx);
                ls += e0 + e1;
                *(float4*)&Sdup[sr*SDS + cc + 4*j] = make_float4(e0, e0, e1, e1);
            }
            ls += __shfl_xor_sync(0xffffffffu, ls, 1);
            ls += __shfl_xor_sync(0xffffffffu, ls, 2);
            if ((t & 3) == 0) {
                float f = __expf(mold - mx);
                rowl[sr] = rowl[sr]*f + ls;
                rowm[sr] = mx;
                rowf[sr] = f;
            }
        }
        __syncthreads();
        // ---- O = O*f + P V ----
        #pragma unroll
        for (int i = 0; i < 4; i++) {
            u64 f2 = bcast2(rowf[q0 + i]);
            #pragma unroll
            for (int c = 0; c < 4; c++) mul2(oacc[i][c], f2);
        }
        #pragma unroll 4
        for (int kk = 0; kk < 32; kk++) {
            ulonglong2 v0 = *(const ulonglong2*)&Vs[kk*VSS + pd0];
            ulonglong2 v1 = *(const ulonglong2*)&Vs[kk*VSS + pd1];
            #pragma unroll
            for (int i = 0; i < 4; i++) {
                u64 p2 = *(const u64*)&Sdup[(q0+i)*SDS + 2*kk];
                ffma2(oacc[i][0], p2, v0.x);
                ffma2(oacc[i][1], p2, v0.y);
                ffma2(oacc[i][2], p2, v1.x);
                ffma2(oacc[i][3], p2, v1.y);
            }
        }
        __syncthreads();
        // ---- store prefetched tile ----
        if (kb1 < 128) {
            #pragma unroll
            for (int l = 0; l < 4; l++) {
                int f4 = t + l*256;
                int r = f4 >> 3, c = f4 & 7;
                float4 v = kreg[l];
                *(float4*)&Kdup[r*KDS + 8*c]     = make_float4(v.x, v.x, v.y, v.y);
                *(float4*)&Kdup[r*KDS + 8*c + 4] = make_float4(v.z, v.z, v.w, v.w);
            }
            #pragma unroll
            for (int l = 0; l < 4; l++) {
                int f4 = t + l*256;
                int r = f4 >> 5, c = f4 & 31;
                *(float4*)&Vs[r*VSS + 4*c] = vreg[l];
            }
        }
        __syncthreads();
    }
    #pragma unroll
    for (int i = 0; i < 4; i++) {
        float inv = 1.f / rowl[q0 + i];
        int row = n0 + q0 + i;
        float2 u0 = unpk(oacc[i][0]), u1 = unpk(oacc[i][1]);
        float2 u2 = unpk(oacc[i][2]), u3 = unpk(oacc[i][3]);
        *(float4*)&outp[(size_t)row*512 + coff + pd0] =
            make_float4(u0.x*inv, u0.y*inv, u1.x*inv, u1.y*inv);
        *(float4*)&outp[(size_t)row*512 + coff + pd1] =
            make_float4(u2.x*inv, u2.y*inv, u3.x*inv, u3.y*inv);
    }
}

// ---------------- launch ----------------
extern "C" void kernel_launch(void* const* d_in, const int* in_sizes, int n_in,
                              void* d_out, int out_size) {
    const float* x          = (const float*)d_in[0];
    const int*   ei         = (const int*)  d_in[1];
    const float* sage_wl    = (const float*)d_in[2];
    const float* sage_wr    = (const float*)d_in[3];
    const float* sage_bl    = (const float*)d_in[4];
    const float* ln_g       = (const float*)d_in[5];
    const float* ln_b       = (const float*)d_in[6];
    const float* conv_w     = (const float*)d_in[7];
    const float* conv_b     = (const float*)d_in[8];
    const float* cnorm_g    = (const float*)d_in[9];
    const float* cnorm_b    = (const float*)d_in[10];
    const float* in_proj_w  = (const float*)d_in[11];
    const float* in_proj_b  = (const float*)d_in[12];
    const float* out_proj_w = (const float*)d_in[13];
    const float* out_proj_b = (const float*)d_in[14];
    const float* anorm_g    = (const float*)d_in[15];
    const float* anorm_b    = (const float*)d_in[16];
    const float* fuse_w     = (const float*)d_in[17];
    const float* fuse_b     = (const float*)d_in[18];
    float* outp = (float*)d_out;

    float *ph, *pagg, *ptmp, *pca, *pcb, *pqkv, *pqkt, *pattn, *po, *po2;
    cudaGetSymbolAddress((void**)&ph,     g_h);
    cudaGetSymbolAddress((void**)&pagg,   g_agg);
    cudaGetSymbolAddress((void**)&ptmp,   g_tmp);
    cudaGetSymbolAddress((void**)&pca,    g_ca);
    cudaGetSymbolAddress((void**)&pcb,    g_cb);
    cudaGetSymbolAddress((void**)&pqkv,   g_qkv);
    cudaGetSymbolAddress((void**)&pqkt,   g_qkt);
    cudaGetSymbolAddress((void**)&pattn,  g_attn);
    cudaGetSymbolAddress((void**)&po,     g_o);
    cudaGetSymbolAddress((void**)&po2,    g_o2);

    // CSR build
    k_zero<<<16, 256>>>();
    k_count<<<E_EDGES/256, 256>>>(ei + E_EDGES);
    k_scan<<<1, 1024>>>();
    k_fill<<<E_EDGES/256, 256>>>(ei, ei + E_EDGES);

    dim3 g_hh(H/BN, N_NODES/BM);   // (2, 64)

    // ---- GNN: 6 SAGE layers (K=512: [agg|h] x [wl;wr]) ----
    const float* hcur = x;
    for (int i = 0; i < 6; i++) {
        k_agg<<<N_NODES, 256>>>(hcur, pagg);
        k_sgemm<<<g_hh, 256>>>(pagg, H, 0, hcur, H, 0, pagg, H, 0,
                               sage_wl + (size_t)i*H*H, sage_wr + (size_t)i*H*H,
                               sage_wl, H, 1,
                               ptmp, H, N_NODES, 2*H, H, sage_bl + i*H);
        int flags = (i < 5) ? (F_LN | F_POSTRELU | F_RES) : (F_POSTRELU | F_RES);
        k_ln<<<N_NODES, 256>>>(ptmp, (i < 5) ? ln_g + i*H : nullptr,
                               (i < 5) ? ln_b + i*H : nullptr,
                               hcur, ph, H, flags);
        hcur = ph;
    }

    // ---- CNN branch: 3 conv1d (K=3 taps, pad 1) — one K=768 GEMM each ----
    const float* cin = ph;
    float* couts[3] = {pca, pcb, pca};
    for (int j = 0; j < 3; j++) {
        const float* wj = conv_w + (size_t)j*H*H*3;
        k_sgemm<<<g_hh, 256>>>(cin, H, -1, cin, H, 0, cin, H, 1,
                               wj + 0, wj + 1, wj + 2, 3*H, 3,
                               ptmp, H, N_NODES, 3*H, H, conv_b + j*H);
        k_ln<<<N_NODES, 256>>>(ptmp, cnorm_g + j*H, cnorm_b + j*H,
                               nullptr, couts[j], H, F_LN | F_PRERELU);
        cin = couts[j];
    }

    // ---- qkv projection (virtual concat, K=512) ----
    dim3 g_qkvd(1536/BN, N_NODES/BM);
    k_sgemm<<<g_qkvd, 256>>>(ph, H, 0, cin, H, 0, ph, H, 0,
                             in_proj_w, in_proj_w + 256, in_proj_w, 512, 1,
                             pqkv, 1536, N_NODES, 512, 1536, in_proj_b);

    // ---- transpose Q,K ----
    dim3 g_tr(N_NODES/32, 32);
    k_qkT<<<g_tr, 256>>>(pqkv, pqkt);

    // ---- flash attention ----
    cudaFuncSetAttribute(k_flash, cudaFuncAttributeMaxDynamicSharedMemorySize, FLASH_SMEM);
    dim3 g_fl(64, 4);
    k_flash<<<g_fl, 256, FLASH_SMEM>>>(pqkv, pqkt, pattn);

    // ---- out_proj + LN + fuse ----
    dim3 g_op(512/BN, N_NODES/BM);
    k_sgemm<<<g_op, 256>>>(pattn, 512, 0, pattn + 256, 512, 0, pattn, 512, 0,
                           out_proj_w, out_proj_w + 256, out_proj_w, 512, 1,
                           po, 512, N_NODES, 512, 512, out_proj_b);
    k_ln<<<N_NODES, 256>>>(po, anorm_g, anorm_b, nullptr, po2, 512, F_LN);
    dim3 g_fu(1, N_NODES/BM);
    k_sgemm<<<g_fu, 256>>>(po2, 512, 0, po2 + 256, 512, 0, po2, 512, 0,
                           fuse_w, fuse_w + 256, fuse_w, 512, 1,
                           outp, 64, N_NODES, 512, 64, fuse_b);
}

// round 10
// speedup vs baseline: 1.3495x; 1.3495x over previous
#include <cuda_runtime.h>
#include <cuda_bf16.h>
#include <math.h>
#include <stdint.h>

#define N_NODES 4096
#define H 256
#define E_EDGES 131072

typedef unsigned long long u64;

__device__ __forceinline__ void ffma2(u64 &d, u64 a, u64 b) {
    asm("fma.rn.f32x2 %0, %1, %2, %0;" : "+l"(d) : "l"(a), "l"(b));
}
__device__ __forceinline__ void mul2(u64 &d, u64 a) {
    asm("mul.rn.f32x2 %0, %0, %1;" : "+l"(d) : "l"(a));
}
__device__ __forceinline__ u64 bcast2(float x) {
    u64 r; asm("mov.b64 %0, {%1, %1};" : "=l"(r) : "f"(x)); return r;
}
__device__ __forceinline__ float2 unpk(u64 v) {
    float2 r; asm("mov.b64 {%0, %1}, %2;" : "=f"(r.x), "=f"(r.y) : "l"(v)); return r;
}
__device__ __forceinline__ uint32_t s2u(const void* p) {
    uint32_t a;
    asm("{ .reg .u64 t; cvta.to.shared.u64 t, %1; cvt.u32.u64 %0, t; }"
        : "=r"(a) : "l"(p));
    return a;
}
__device__ __forceinline__ void ldsm4(uint32_t (&r)[4], uint32_t addr) {
    asm volatile("ldmatrix.sync.aligned.m8n8.x4.shared.b16 {%0,%1,%2,%3}, [%4];"
                 : "=r"(r[0]), "=r"(r[1]), "=r"(r[2]), "=r"(r[3]) : "r"(addr));
}
__device__ __forceinline__ void mma16816(float (&d)[4], const uint32_t (&a)[4],
                                         uint32_t b0, uint32_t b1) {
    asm volatile(
        "mma.sync.aligned.m16n8k16.row.col.f32.bf16.bf16.f32 "
        "{%0,%1,%2,%3}, {%4,%5,%6,%7}, {%8,%9}, {%0,%1,%2,%3};"
        : "+f"(d[0]), "+f"(d[1]), "+f"(d[2]), "+f"(d[3])
        : "r"(a[0]), "r"(a[1]), "r"(a[2]), "r"(a[3]), "r"(b0), "r"(b1));
}

// ---------------- scratch ----------------
__device__ float g_h[N_NODES*H];
__device__ float g_agg[N_NODES*H];
__device__ float g_tmp[N_NODES*H];
__device__ float g_ca[N_NODES*H];
__device__ float g_cb[N_NODES*H];
__device__ float g_qkv[N_NODES*6*H];
__device__ float g_qkt[8*128*N_NODES];
__device__ float g_attn[N_NODES*2*H];
__device__ float g_o[N_NODES*2*H];
__device__ float g_o2[N_NODES*2*H];
__device__ int   g_cnt[N_NODES];
__device__ int   g_fillp[N_NODES];
__device__ int   g_off[N_NODES+1];
__device__ int   g_csrs[E_EDGES];
__device__ float g_degf[N_NODES];

// ---------------- CSR build ----------------
__global__ void k_zero() {
    int i = blockIdx.x*256 + threadIdx.x;
    if (i < N_NODES) { g_cnt[i] = 0; g_fillp[i] = 0; }
}
__global__ void k_count(const int* __restrict__ dst) {
    int e = blockIdx.x*256 + threadIdx.x;
    if (e < E_EDGES) atomicAdd(&g_cnt[dst[e]], 1);
}
__global__ void k_scan() {
    __shared__ int ps[1024];
    int t = threadIdx.x;
    int c[4]; int s = 0;
    #pragma unroll
    for (int l = 0; l < 4; l++) { c[l] = g_cnt[t*4+l]; s += c[l]; }
    ps[t] = s;
    __syncthreads();
    for (int d = 1; d < 1024; d <<= 1) {
        int v = (t >= d) ? ps[t-d] : 0;
        __syncthreads();
        ps[t] += v;
        __syncthreads();
    }
    int base = ps[t] - s;
    #pragma unroll
    for (int l = 0; l < 4; l++) {
        g_off[t*4+l] = base;
        base += c[l];
        g_degf[t*4+l] = (float)max(c[l], 1);
    }
    if (t == 1023) g_off[N_NODES] = ps[1023];
}
__global__ void k_fill(const int* __restrict__ src, const int* __restrict__ dst) {
    int e = blockIdx.x*256 + threadIdx.x;
    if (e < E_EDGES) {
        int d = dst[e];
        int p = atomicAdd(&g_fillp[d], 1);
        g_csrs[g_off[d] + p] = src[e];
    }
}

// ---------------- Q/K transpose ----------------
__global__ __launch_bounds__(256) void k_qkT(const float* __restrict__ qkv,
                                             float* __restrict__ qkt) {
    __shared__ float tile[32][33];
    int nt = blockIdx.x*32;
    int dt = blockIdx.y*32;
    int g  = dt >> 7;
    int cb = (g >> 2)*512 + (g & 3)*128 + (dt & 127);
    int tx = threadIdx.x & 31, ty = threadIdx.x >> 5;
    #pragma unroll
    for (int i = 0; i < 4; i++)
        tile[ty + i*8][tx] = qkv[(size_t)(nt + ty + i*8)*1536 + cb + tx];
    __syncthreads();
    #pragma unroll
    for (int i = 0; i < 4; i++)
        qkt[(size_t)(dt + ty + i*8)*N_NODES + nt + tx] = tile[tx][ty + i*8];
}

// ---------------- mean aggregation ----------------
__global__ __launch_bounds__(256) void k_agg(const float* __restrict__ h,
                                             float* __restrict__ agg) {
    int n = blockIdx.x;
    int f = threadIdx.x;
    int s = g_off[n], e = g_off[n+1];
    __shared__ int nb[256];
    float acc = 0.f;
    for (int base = s; base < e; base += 256) {
        int m = min(256, e - base);
        if (f < m) nb[f] = g_csrs[base + f];
        __syncthreads();
        for (int j = 0; j < m; j++)
            acc += h[(size_t)nb[j]*H + f];
        __syncthreads();
    }
    agg[(size_t)n*H + f] = acc / g_degf[n];
}

// ---------------- HMMA split-bf16 GEMM ----------------
// C[M, Ncols] = [A0|A1|A2](fp32) @ [B0;B1;B2](fp32, elem-stride es)^T + bias
// Split x = hi + lo (bf16); D += AhBh + AhBl + AlBh (ll dropped, ~2^-18 rel).
// BM=64, BN=64, BK=32, 128 threads = 4 warps (2x2 of 32x32 warp tiles).
// smem swizzle: granule g' = g ^ ((row>>1)&3); bank-clean stores + ldmatrix.

__device__ __forceinline__ uint32_t soff(int row, int g) {
    return (uint32_t)(row*32 + ((g ^ ((row >> 1) & 3)) << 3));
}
__device__ __forceinline__ void cvt8(const float4 v0, const float4 v1,
                                     uint4 &hi, uint4 &lo) {
    __nv_bfloat162 h0 = __float22bfloat162_rn(make_float2(v0.x, v0.y));
    __nv_bfloat162 h1 = __float22bfloat162_rn(make_float2(v0.z, v0.w));
    __nv_bfloat162 h2 = __float22bfloat162_rn(make_float2(v1.x, v1.y));
    __nv_bfloat162 h3 = __float22bfloat162_rn(make_float2(v1.z, v1.w));
    float2 f0 = __bfloat1622float2(h0), f1 = __bfloat1622float2(h1);
    float2 f2 = __bfloat1622float2(h2), f3 = __bfloat1622float2(h3);
    __nv_bfloat162 l0 = __float22bfloat162_rn(make_float2(v0.x - f0.x, v0.y - f0.y));
    __nv_bfloat162 l1 = __float22bfloat162_rn(make_float2(v0.z - f1.x, v0.w - f1.y));
    __nv_bfloat162 l2 = __float22bfloat162_rn(make_float2(v1.x - f2.x, v1.y - f2.y));
    __nv_bfloat162 l3 = __float22bfloat162_rn(make_float2(v1.z - f3.x, v1.w - f3.y));
    hi = make_uint4(*(uint32_t*)&h0, *(uint32_t*)&h1, *(uint32_t*)&h2, *(uint32_t*)&h3);
    lo = make_uint4(*(uint32_t*)&l0, *(uint32_t*)&l1, *(uint32_t*)&l2, *(uint32_t*)&l3);
}

__global__ __launch_bounds__(128) void k_mma(
    const float* __restrict__ A0, int ld0, int sh0,
    const float* __restrict__ A1, int ld1, int sh1,
    const float* __restrict__ A2, int ld2, int sh2,
    const float* __restrict__ B0, const float* __restrict__ B1,
    const float* __restrict__ B2, int ldb, int es,
    float* __restrict__ C, int ldc, int M, int K,
    const float* __restrict__ bias)
{
    __shared__ __nv_bfloat16 Ah[2048], Al[2048], Bh[2048], Bl[2048];
    int t = threadIdx.x, w = t >> 5, lane = t & 31;
    int bm = blockIdx.y*64, bn = blockIdx.x*64;
    int wm = (w & 1)*32, wn = (w >> 1)*32;

    float d[2][4][4] = {};

    uint32_t ahB = s2u(Ah), alB = s2u(Al), bhB = s2u(Bh), blB = s2u(Bl);
    int arow = wm + (lane & 15);                       // + mt*16
    int ag   = lane >> 4;                              // + ks*2
    int brow = wn + ((lane >> 4) << 3) + (lane & 7);   // + nb*16
    int bg   = (lane >> 3) & 1;                        // + ks*2

    for (int k0 = 0; k0 < K; k0 += 32) {
        int seg = k0 >> 8;
        const float* A = (seg == 0) ? A0 : (seg == 1) ? A1 : A2;
        int lda = (seg == 0) ? ld0 : (seg == 1) ? ld1 : ld2;
        int sh  = (seg == 0) ? sh0 : (seg == 1) ? sh1 : sh2;
        const float* B = (seg == 0) ? B0 : (seg == 1) ? B1 : B2;
        int kc = k0 & 255;

        // ---- load + convert A (64 rows x 32 k): 2 granules/thread ----
        #pragma unroll
        for (int l = 0; l < 2; l++) {
            int gid = t + l*128;
            int row = gid >> 2, g = gid & 3;
            int gr = bm + row + sh;
            float4 v0 = make_float4(0.f,0.f,0.f,0.f), v1 = v0;
            if (gr >= 0 && gr < M) {
                const float* ap = A + (size_t)gr*lda + kc + g*8;
                v0 = *(const float4*)ap;
                v1 = *(const float4*)(ap + 4);
            }
            uint4 hi, lo;
            cvt8(v0, v1, hi, lo);
            uint32_t off = soff(row, g);
            *(uint4*)&Ah[off] = hi;
            *(uint4*)&Al[off] = lo;
        }
        // ---- load + convert B (64 n-rows x 32 k) ----
        #pragma unroll
        for (int l = 0; l < 2; l++) {
            int gid = t + l*128;
            int row = gid >> 2, g = gid & 3;
            const float* bp = B + (size_t)(bn + row)*ldb;
            float4 v0, v1;
            if (es == 1) {
                v0 = *(const float4*)(bp + kc + g*8);
                v1 = *(const float4*)(bp + kc + g*8 + 4);
            } else {
                float vv[8];
                #pragma unroll
                for (int j = 0; j < 8; j++)
                    vv[j] = bp[(size_t)(kc + g*8 + j)*es];
                v0 = make_float4(vv[0], vv[1], vv[2], vv[3]);
                v1 = make_float4(vv[4], vv[5], vv[6], vv[7]);
            }
            uint4 hi, lo;
            cvt8(v0, v1, hi, lo);
            uint32_t off = soff(row, g);
            *(uint4*)&Bh[off] = hi;
            *(uint4*)&Bl[off] = lo;
        }
        __syncthreads();
        // ---- 3 passes: Ah*Bh, Ah*Bl, Al*Bh ----
        #pragma unroll
        for (int pass = 0; pass < 3; pass++) {
            uint32_t aB = (pass == 2) ? alB : ahB;
            uint32_t bB = (pass == 1) ? blB : bhB;
            #pragma unroll
            for (int ks = 0; ks < 2; ks++) {
                uint32_t afr[2][4], bfr[2][4];
                #pragma unroll
                for (int mt = 0; mt < 2; mt++)
                    ldsm4(afr[mt], aB + soff(arow + mt*16, ag + ks*2)*2);
                #pragma unroll
                for (int nb2 = 0; nb2 < 2; nb2++)
                    ldsm4(bfr[nb2], bB + soff(brow + nb2*16, bg + ks*2)*2);
                #pragma unroll
                for (int mt = 0; mt < 2; mt++) {
                    mma16816(d[mt][0], afr[mt], bfr[0][0], bfr[0][1]);
                    mma16816(d[mt][1], afr[mt], bfr[0][2], bfr[0][3]);
                    mma16816(d[mt][2], afr[mt], bfr[1][0], bfr[1][1]);
                    mma16816(d[mt][3], afr[mt], bfr[1][2], bfr[1][3]);
                }
            }
        }
        __syncthreads();
    }

    // ---- epilogue: fragment rows/cols + bias ----
    int r0 = bm + wm + (lane >> 2);
    int c0 = bn + wn + (lane & 3)*2;
    #pragma unroll
    for (int mt = 0; mt < 2; mt++) {
        #pragma unroll
        for (int nt = 0; nt < 4; nt++) {
            int row = r0 + mt*16, col = c0 + nt*8;
            float2 bs = *(const float2*)&bias[col];
            *(float2*)&C[(size_t)row*ldc + col] =
                make_float2(d[mt][nt][0] + bs.x, d[mt][nt][1] + bs.y);
            *(float2*)&C[(size_t)(row + 8)*ldc + col] =
                make_float2(d[mt][nt][2] + bs.x, d[mt][nt][3] + bs.y);
        }
    }
}

// ---------------- LayerNorm / activation ----------------
#define F_LN       1
#define F_POSTRELU 2
#define F_RES      4
#define F_PRERELU  8

__global__ __launch_bounds__(256) void k_ln(
    const float* __restrict__ x, const float* __restrict__ g, const float* __restrict__ b,
    const float* __restrict__ res, float* __restrict__ out, int W, int flags)
{
    __shared__ float rs[8], rq[8];
    __shared__ float s_mean, s_rstd;
    int row = blockIdx.x, t = threadIdx.x;
    const float* xr = x + (size_t)row*W;
    int two = (W == 512);
    float v0 = xr[t];
    float v1 = two ? xr[t + 256] : 0.f;
    if (flags & F_PRERELU) { v0 = fmaxf(v0, 0.f); v1 = fmaxf(v1, 0.f); }
    float s = v0 + v1, sq = v0*v0 + v1*v1;
    #pragma unroll
    for (int o = 16; o > 0; o >>= 1) {
        s  += __shfl_xor_sync(0xffffffff, s,  o);
        sq += __shfl_xor_sync(0xffffffff, sq, o);
    }
    int warp = t >> 5, lane = t & 31;
    if (lane == 0) { rs[warp] = s; rq[warp] = sq; }
    __syncthreads();
    if (t == 0) {
        float S = 0.f, Q = 0.f;
        #pragma unroll
        for (int w = 0; w < 8; w++) { S += rs[w]; Q += rq[w]; }
        float mean = S / (float)W;
        float var = fmaxf(Q / (float)W - mean*mean, 0.f);
        s_mean = mean;
        s_rstd = rsqrtf(var + 1e-5f);
    }
    __syncthreads();
    float mean = s_mean, rstd = s_rstd;

    float val = v0;
    if (flags & F_LN)       val = (val - mean)*rstd*g[t] + b[t];
    if (flags & F_POSTRELU) val = fmaxf(val, 0.f);
    if (flags & F_RES)      val += res[(size_t)row*W + t];
    out[(size_t)row*W + t] = val;

    if (two) {
        int c = t + 256;
        float val2 = v1;
        if (flags & F_LN)       val2 = (val2 - mean)*rstd*g[c] + b[c];
        if (flags & F_POSTRELU) val2 = fmaxf(val2, 0.f);
        if (flags & F_RES)      val2 += res[(size_t)row*W + c];
        out[(size_t)row*W + c] = val2;
    }
}

// ---------------- flash attention (f32x2, dup operands — round-7 version) ----------------
#define QDS 132
#define KTS 68
#define VSS 132
#define SDS 132
#define OFF_KT (128*QDS)
#define OFF_V  (OFF_KT + 128*KTS)
#define OFF_S  (OFF_V + 64*VSS)
#define OFF_R  (OFF_S + 64*SDS)
#define FLASH_SMEM ((OFF_R + 192)*4)

__global__ __launch_bounds__(256, 1) void k_flash(const float* __restrict__ qkv,
                                                  const float* __restrict__ qkt,
                                                  float* __restrict__ outp)
{
    extern __shared__ float sm[];
    float* Qtd  = sm;
    float* Kt   = sm + OFF_KT;
    float* Vs   = sm + OFF_V;
    float* Sdup = sm + OFF_S;
    float* rowm = sm + OFF_R;
    float* rowl = rowm + 64;
    float* rowf = rowl + 64;

    int qb = blockIdx.x, head = blockIdx.y, t = threadIdx.x;
    int n0 = qb*64, coff = head*128;
    int qg = t >> 4, kg = t & 15;
    int q0 = qg*4;
    int kqa = 2*kg, kqb = 32 + 2*kg;
    int pd0 = 4*kg, pd1 = 64 + 4*kg;

    const float* Qg = qkt + (size_t)head*128*N_NODES + n0;
    #pragma unroll
    for (int l = 0; l < 8; l++) {
        int f4 = t + l*256;
        int r = f4 >> 4, c = f4 & 15;
        float4 v = *(const float4*)&Qg[(size_t)r*N_NODES + c*4];
        *(float4*)&Qtd[r*QDS + 8*c]     = make_float4(v.x, v.x, v.y, v.y);
        *(float4*)&Qtd[r*QDS + 8*c + 4] = make_float4(v.z, v.z, v.w, v.w);
    }
    if (t < 64) { rowm[t] = -1e30f; rowl[t] = 0.f; }

    u64 oacc[4][4];
    #pragma unroll
    for (int i = 0; i < 4; i++)
        #pragma unroll
        for (int c = 0; c < 4; c++) oacc[i][c] = 0ULL;

    const float scale = 0.08838834764831845f;
    const float* Kg = qkt + (size_t)(4 + head)*128*N_NODES;

    for (int kb = 0; kb < 64; kb++) {
        __syncthreads();
        #pragma unroll
        for (int l = 0; l < 8; l++) {
            int f4 = t + l*256;
            int r = f4 >> 4, c = f4 & 15;
            *(float4*)&Kt[r*KTS + 4*c] =
                *(const float4*)&Kg[(size_t)r*N_NODES + kb*64 + 4*c];
        }
        #pragma unroll
        for (int l = 0; l < 8; l++) {
            int f4 = t + l*256;
            int r = f4 >> 5, c = f4 & 31;
            *(float4*)&Vs[r*VSS + 4*c] =
                *(const float4*)&qkv[(size_t)(kb*64 + r)*1536 + 1024 + coff + 4*c];
        }
        __syncthreads();
        u64 sacc[4][2];
        #pragma unroll
        for (int i = 0; i < 4; i++) { sacc[i][0] = 0ULL; sacc[i][1] = 0ULL; }
        #pragma unroll 4
        for (int d = 0; d < 128; d++) {
            ulonglong2 qa = *(const ulonglong2*)&Qtd[d*QDS + 2*q0];
            ulonglong2 qb2 = *(const ulonglong2*)&Qtd[d*QDS + 2*q0 + 4];
            u64 ka = *(const u64*)&Kt[d*KTS + kqa];
            u64 kb2 = *(const u64*)&Kt[d*KTS + kqb];
            ffma2(sacc[0][0], qa.x,  ka);  ffma2(sacc[0][1], qa.x,  kb2);
            ffma2(sacc[1][0], qa.y,  ka);  ffma2(sacc[1][1], qa.y,  kb2);
            ffma2(sacc[2][0], qb2.x, ka);  ffma2(sacc[2][1], qb2.x, kb2);
            ffma2(sacc[3][0], qb2.y, ka);  ffma2(sacc[3][1], qb2.y, kb2);
        }
        #pragma unroll
        for (int i = 0; i < 4; i++) {
            float2 ua = unpk(sacc[i][0]);
            float2 ub = unpk(sacc[i][1]);
            *(float4*)&Sdup[(q0+i)*SDS + 4*kg] =
                make_float4(ua.x*scale, ua.x*scale, ua.y*scale, ua.y*scale);
            *(float4*)&Sdup[(q0+i)*SDS + 64 + 4*kg] =
                make_float4(ub.x*scale, ub.x*scale, ub.y*scale, ub.y*scale);
        }
        __syncthreads();
        {
            int sr = t >> 2, cc = (t & 3)*4;
            float4 v[8];
            float mold = rowm[sr];
            float mx = mold;
            #pragma unroll
            for (int u2 = 0; u2 < 8; u2++) {
                v[u2] = *(float4*)&Sdup[sr*SDS + cc + u2*16];
                mx = fmaxf(mx, fmaxf(v[u2].x, v[u2].z));
            }
            mx = fmaxf(mx, __shfl_xor_sync(0xffffffffu, mx, 1));
            mx = fmaxf(mx, __shfl_xor_sync(0xffffffffu, mx, 2));
            float ls = 0.f;
            #pragma unroll
            for (int u2 = 0; u2 < 8; u2++) {
                float e0 = __expf(v[u2].x - mx);
                float e1 = __expf(v[u2].z - mx);
                ls += e0 + e1;
                *(float4*)&Sdup[sr*SDS + cc + u2*16] = make_float4(e0, e0, e1, e1);
            }
            ls += __shfl_xor_sync(0xffffffffu, ls, 1);
            ls += __shfl_xor_sync(0xffffffffu, ls, 2);
            if ((t & 3) == 0) {
                float f = __expf(mold - mx);
                rowl[sr] = rowl[sr]*f + ls;
                rowm[sr] = mx;
                rowf[sr] = f;
            }
        }
        __syncthreads();
        #pragma unroll
        for (int i = 0; i < 4; i++) {
            u64 f2 = bcast2(rowf[q0 + i]);
            #pragma unroll
            for (int c = 0; c < 4; c++) mul2(oacc[i][c], f2);
        }
        #pragma unroll 2
        for (int kk = 0; kk < 64; kk++) {
            ulonglong2 v0 = *(const ulonglong2*)&Vs[kk*VSS + pd0];
            ulonglong2 v1 = *(const ulonglong2*)&Vs[kk*VSS + pd1];
            #pragma unroll
            for (int i = 0; i < 4; i++) {
                u64 p2 = *(const u64*)&Sdup[(q0+i)*SDS + 2*kk];
                ffma2(oacc[i][0], p2, v0.x);
                ffma2(oacc[i][1], p2, v0.y);
                ffma2(oacc[i][2], p2, v1.x);
                ffma2(oacc[i][3], p2, v1.y);
            }
        }
    }
    #pragma unroll
    for (int i = 0; i < 4; i++) {
        float inv = 1.f / rowl[q0 + i];
        int row = n0 + q0 + i;
        float2 u0 = unpk(oacc[i][0]), u1 = unpk(oacc[i][1]);
        float2 u2 = unpk(oacc[i][2]), u3 = unpk(oacc[i][3]);
        *(float4*)&outp[(size_t)row*512 + coff + pd0] =
            make_float4(u0.x*inv, u0.y*inv, u1.x*inv, u1.y*inv);
        *(float4*)&outp[(size_t)row*512 + coff + pd1] =
            make_float4(u2.x*inv, u2.y*inv, u3.x*inv, u3.y*inv);
    }
}

// ---------------- launch ----------------
extern "C" void kernel_launch(void* const* d_in, const int* in_sizes, int n_in,
                              void* d_out, int out_size) {
    const float* x          = (const float*)d_in[0];
    const int*   ei         = (const int*)  d_in[1];
    const float* sage_wl    = (const float*)d_in[2];
    const float* sage_wr    = (const float*)d_in[3];
    const float* sage_bl    = (const float*)d_in[4];
    const float* ln_g       = (const float*)d_in[5];
    const float* ln_b       = (const float*)d_in[6];
    const float* conv_w     = (const float*)d_in[7];
    const float* conv_b     = (const float*)d_in[8];
    const float* cnorm_g    = (const float*)d_in[9];
    const float* cnorm_b    = (const float*)d_in[10];
    const float* in_proj_w  = (const float*)d_in[11];
    const float* in_proj_b  = (const float*)d_in[12];
    const float* out_proj_w = (const float*)d_in[13];
    const float* out_proj_b = (const float*)d_in[14];
    const float* anorm_g    = (const float*)d_in[15];
    const float* anorm_b    = (const float*)d_in[16];
    const float* fuse_w     = (const float*)d_in[17];
    const float* fuse_b     = (const float*)d_in[18];
    float* outp = (float*)d_out;

    float *ph, *pagg, *ptmp, *pca, *pcb, *pqkv, *pqkt, *pattn, *po, *po2;
    cudaGetSymbolAddress((void**)&ph,     g_h);
    cudaGetSymbolAddress((void**)&pagg,   g_agg);
    cudaGetSymbolAddress((void**)&ptmp,   g_tmp);
    cudaGetSymbolAddress((void**)&pca,    g_ca);
    cudaGetSymbolAddress((void**)&pcb,    g_cb);
    cudaGetSymbolAddress((void**)&pqkv,   g_qkv);
    cudaGetSymbolAddress((void**)&pqkt,   g_qkt);
    cudaGetSymbolAddress((void**)&pattn,  g_attn);
    cudaGetSymbolAddress((void**)&po,     g_o);
    cudaGetSymbolAddress((void**)&po2,    g_o2);

    cudaFuncSetAttribute(k_flash, cudaFuncAttributeMaxDynamicSharedMemorySize, FLASH_SMEM);

    // CSR build
    k_zero<<<16, 256>>>();
    k_count<<<E_EDGES/256, 256>>>(ei + E_EDGES);
    k_scan<<<1, 1024>>>();
    k_fill<<<E_EDGES/256, 256>>>(ei, ei + E_EDGES);

    dim3 g_hh(4, 64);   // (256/64, 4096/64)

    // ---- GNN: 6 SAGE layers (K=512: [agg|h] x [wl;wr]) ----
    const float* hcur = x;
    for (int i = 0; i < 6; i++) {
        k_agg<<<N_NODES, 256>>>(hcur, pagg);
        k_mma<<<g_hh, 128>>>(
            pagg, H, 0, hcur, H, 0, pagg, H, 0,
            sage_wl + (size_t)i*H*H, sage_wr + (size_t)i*H*H, sage_wl, H, 1,
            ptmp, H, N_NODES, 2*H, sage_bl + i*H);
        int flags = (i < 5) ? (F_LN | F_POSTRELU | F_RES) : (F_POSTRELU | F_RES);
        k_ln<<<N_NODES, 256>>>(ptmp, (i < 5) ? ln_g + i*H : nullptr,
                               (i < 5) ? ln_b + i*H : nullptr,
                               hcur, ph, H, flags);
        hcur = ph;
    }

    // ---- CNN branch: 3 conv1d (K=3 taps, pad 1) — one K=768 GEMM each ----
    const float* cin = ph;
    float* couts[3] = {pca, pcb, pca};
    for (int j = 0; j < 3; j++) {
        const float* wj = conv_w + (size_t)j*H*H*3;
        k_mma<<<g_hh, 128>>>(
            cin, H, -1, cin, H, 0, cin, H, 1,
            wj + 0, wj + 1, wj + 2, 3*H, 3,
            ptmp, H, N_NODES, 3*H, conv_b + j*H);
        k_ln<<<N_NODES, 256>>>(ptmp, cnorm_g + j*H, cnorm_b + j*H,
                               nullptr, couts[j], H, F_LN | F_PRERELU);
        cin = couts[j];
    }

    // ---- qkv projection (virtual concat, K=512) ----
    dim3 g_qkvd(24, 64);
    k_mma<<<g_qkvd, 128>>>(
        ph, H, 0, cin, H, 0, ph, H, 0,
        in_proj_w, in_proj_w + 256, in_proj_w, 512, 1,
        pqkv, 1536, N_NODES, 512, in_proj_b);

    // ---- transpose Q,K ----
    dim3 g_tr(N_NODES/32, 32);
    k_qkT<<<g_tr, 256>>>(pqkv, pqkt);

    // ---- flash attention ----
    dim3 g_fl(64, 4);
    k_flash<<<g_fl, 256, FLASH_SMEM>>>(pqkv, pqkt, pattn);

    // ---- out_proj + LN + fuse ----
    dim3 g_op(8, 64);
    k_mma<<<g_op, 128>>>(
        pattn, 512, 0, pattn + 256, 512, 0, pattn, 512, 0,
        out_proj_w, out_proj_w + 256, out_proj_w, 512, 1,
        po, 512, N_NODES, 512, out_proj_b);
    k_ln<<<N_NODES, 256>>>(po, anorm_g, anorm_b, nullptr, po2, 512, F_LN);
    dim3 g_fu(1, 64);
    k_mma<<<g_fu, 128>>>(
        po2, 512, 0, po2 + 256, 512, 0, po2, 512, 0,
        fuse_w, fuse_w + 256, fuse_w, 512, 1,
        outp, 64, N_NODES, 512, fuse_b);
}

// round 11
// speedup vs baseline: 2.4717x; 1.8315x over previous
#include <cuda_runtime.h>
#include <cuda_bf16.h>
#include <math.h>
#include <stdint.h>

#define N_NODES 4096
#define H 256
#define E_EDGES 131072

typedef unsigned long long u64;

__device__ __forceinline__ uint32_t s2u(const void* p) {
    uint32_t a;
    asm("{ .reg .u64 t; cvta.to.shared.u64 t, %1; cvt.u32.u64 %0, t; }"
        : "=r"(a) : "l"(p));
    return a;
}
__device__ __forceinline__ void ldsm4(uint32_t (&r)[4], uint32_t addr) {
    asm volatile("ldmatrix.sync.aligned.m8n8.x4.shared.b16 {%0,%1,%2,%3}, [%4];"
                 : "=r"(r[0]), "=r"(r[1]), "=r"(r[2]), "=r"(r[3]) : "r"(addr));
}
__device__ __forceinline__ void mma16816(float (&d)[4], const uint32_t (&a)[4],
                                         uint32_t b0, uint32_t b1) {
    asm volatile(
        "mma.sync.aligned.m16n8k16.row.col.f32.bf16.bf16.f32 "
        "{%0,%1,%2,%3}, {%4,%5,%6,%7}, {%8,%9}, {%0,%1,%2,%3};"
        : "+f"(d[0]), "+f"(d[1]), "+f"(d[2]), "+f"(d[3])
        : "r"(a[0]), "r"(a[1]), "r"(a[2]), "r"(a[3]), "r"(b0), "r"(b1));
}

// ---------------- scratch ----------------
__device__ float g_h[N_NODES*H];
__device__ float g_agg[N_NODES*H];
__device__ float g_tmp[N_NODES*H];
__device__ float g_ca[N_NODES*H];
__device__ float g_cb[N_NODES*H];
__device__ float g_qkv[N_NODES*6*H];
__device__ float g_attn[N_NODES*2*H];
__device__ float g_o[N_NODES*2*H];
__device__ float g_o2[N_NODES*2*H];
__device__ __nv_bfloat16 g_qh[4*N_NODES*128];
__device__ __nv_bfloat16 g_ql[4*N_NODES*128];
__device__ __nv_bfloat16 g_kh[4*N_NODES*128];
__device__ __nv_bfloat16 g_kl[4*N_NODES*128];
__device__ __nv_bfloat16 g_vh[512*N_NODES];   // [head][d][n]
__device__ __nv_bfloat16 g_vl[512*N_NODES];
__device__ int   g_cnt[N_NODES];
__device__ int   g_fillp[N_NODES];
__device__ int   g_off[N_NODES+1];
__device__ int   g_csrs[E_EDGES];
__device__ float g_degf[N_NODES];

// ---------------- CSR build ----------------
__global__ void k_zero() {
    int i = blockIdx.x*256 + threadIdx.x;
    if (i < N_NODES) { g_cnt[i] = 0; g_fillp[i] = 0; }
}
__global__ void k_count(const int* __restrict__ dst) {
    int e = blockIdx.x*256 + threadIdx.x;
    if (e < E_EDGES) atomicAdd(&g_cnt[dst[e]], 1);
}
__global__ void k_scan() {
    __shared__ int ps[1024];
    int t = threadIdx.x;
    int c[4]; int s = 0;
    #pragma unroll
    for (int l = 0; l < 4; l++) { c[l] = g_cnt[t*4+l]; s += c[l]; }
    ps[t] = s;
    __syncthreads();
    for (int d = 1; d < 1024; d <<= 1) {
        int v = (t >= d) ? ps[t-d] : 0;
        __syncthreads();
        ps[t] += v;
        __syncthreads();
    }
    int base = ps[t] - s;
    #pragma unroll
    for (int l = 0; l < 4; l++) {
        g_off[t*4+l] = base;
        base += c[l];
        g_degf[t*4+l] = (float)max(c[l], 1);
    }
    if (t == 1023) g_off[N_NODES] = ps[1023];
}
__global__ void k_fill(const int* __restrict__ src, const int* __restrict__ dst) {
    int e = blockIdx.x*256 + threadIdx.x;
    if (e < E_EDGES) {
        int d = dst[e];
        int p = atomicAdd(&g_fillp[d], 1);
        g_csrs[g_off[d] + p] = src[e];
    }
}

// ---------------- mean aggregation ----------------
__global__ __launch_bounds__(256) void k_agg(const float* __restrict__ h,
                                             float* __restrict__ agg) {
    int n = blockIdx.x;
    int f = threadIdx.x;
    int s = g_off[n], e = g_off[n+1];
    __shared__ int nb[256];
    float acc = 0.f;
    for (int base = s; base < e; base += 256) {
        int m = min(256, e - base);
        if (f < m) nb[f] = g_csrs[base + f];
        __syncthreads();
        for (int j = 0; j < m; j++)
            acc += h[(size_t)nb[j]*H + f];
        __syncthreads();
    }
    agg[(size_t)n*H + f] = acc / g_degf[n];
}

// ---------------- HMMA split-bf16 GEMM (round-10, unchanged) ----------------
__device__ __forceinline__ uint32_t soff(int row, int g) {
    return (uint32_t)(row*32 + ((g ^ ((row >> 1) & 3)) << 3));
}
__device__ __forceinline__ void cvt8(const float4 v0, const float4 v1,
                                     uint4 &hi, uint4 &lo) {
    __nv_bfloat162 h0 = __float22bfloat162_rn(make_float2(v0.x, v0.y));
    __nv_bfloat162 h1 = __float22bfloat162_rn(make_float2(v0.z, v0.w));
    __nv_bfloat162 h2 = __float22bfloat162_rn(make_float2(v1.x, v1.y));
    __nv_bfloat162 h3 = __float22bfloat162_rn(make_float2(v1.z, v1.w));
    float2 f0 = __bfloat1622float2(h0), f1 = __bfloat1622float2(h1);
    float2 f2 = __bfloat1622float2(h2), f3 = __bfloat1622float2(h3);
    __nv_bfloat162 l0 = __float22bfloat162_rn(make_float2(v0.x - f0.x, v0.y - f0.y));
    __nv_bfloat162 l1 = __float22bfloat162_rn(make_float2(v0.z - f1.x, v0.w - f1.y));
    __nv_bfloat162 l2 = __float22bfloat162_rn(make_float2(v1.x - f2.x, v1.y - f2.y));
    __nv_bfloat162 l3 = __float22bfloat162_rn(make_float2(v1.z - f3.x, v1.w - f3.y));
    hi = make_uint4(*(uint32_t*)&h0, *(uint32_t*)&h1, *(uint32_t*)&h2, *(uint32_t*)&h3);
    lo = make_uint4(*(uint32_t*)&l0, *(uint32_t*)&l1, *(uint32_t*)&l2, *(uint32_t*)&l3);
}

__global__ __launch_bounds__(128) void k_mma(
    const float* __restrict__ A0, int ld0, int sh0,
    const float* __restrict__ A1, int ld1, int sh1,
    const float* __restrict__ A2, int ld2, int sh2,
    const float* __restrict__ B0, const float* __restrict__ B1,
    const float* __restrict__ B2, int ldb, int es,
    float* __restrict__ C, int ldc, int M, int K,
    const float* __restrict__ bias)
{
    __shared__ __nv_bfloat16 Ah[2048], Al[2048], Bh[2048], Bl[2048];
    int t = threadIdx.x, w = t >> 5, lane = t & 31;
    int bm = blockIdx.y*64, bn = blockIdx.x*64;
    int wm = (w & 1)*32, wn = (w >> 1)*32;

    float d[2][4][4] = {};

    uint32_t ahB = s2u(Ah), alB = s2u(Al), bhB = s2u(Bh), blB = s2u(Bl);
    int arow = wm + (lane & 15);
    int ag   = lane >> 4;
    int brow = wn + ((lane >> 4) << 3) + (lane & 7);
    int bg   = (lane >> 3) & 1;

    for (int k0 = 0; k0 < K; k0 += 32) {
        int seg = k0 >> 8;
        const float* A = (seg == 0) ? A0 : (seg == 1) ? A1 : A2;
        int lda = (seg == 0) ? ld0 : (seg == 1) ? ld1 : ld2;
        int sh  = (seg == 0) ? sh0 : (seg == 1) ? sh1 : sh2;
        const float* B = (seg == 0) ? B0 : (seg == 1) ? B1 : B2;
        int kc = k0 & 255;

        #pragma unroll
        for (int l = 0; l < 2; l++) {
            int gid = t + l*128;
            int row = gid >> 2, g = gid & 3;
            int gr = bm + row + sh;
            float4 v0 = make_float4(0.f,0.f,0.f,0.f), v1 = v0;
            if (gr >= 0 && gr < M) {
                const float* ap = A + (size_t)gr*lda + kc + g*8;
                v0 = *(const float4*)ap;
                v1 = *(const float4*)(ap + 4);
            }
            uint4 hi, lo;
            cvt8(v0, v1, hi, lo);
            uint32_t off = soff(row, g);
            *(uint4*)&Ah[off] = hi;
            *(uint4*)&Al[off] = lo;
        }
        #pragma unroll
        for (int l = 0; l < 2; l++) {
            int gid = t + l*128;
            int row = gid >> 2, g = gid & 3;
            const float* bp = B + (size_t)(bn + row)*ldb;
            float4 v0, v1;
            if (es == 1) {
                v0 = *(const float4*)(bp + kc + g*8);
                v1 = *(const float4*)(bp + kc + g*8 + 4);
            } else {
                float vv[8];
                #pragma unroll
                for (int j = 0; j < 8; j++)
                    vv[j] = bp[(size_t)(kc + g*8 + j)*es];
                v0 = make_float4(vv[0], vv[1], vv[2], vv[3]);
                v1 = make_float4(vv[4], vv[5], vv[6], vv[7]);
            }
            uint4 hi, lo;
            cvt8(v0, v1, hi, lo);
            uint32_t off = soff(row, g);
            *(uint4*)&Bh[off] = hi;
            *(uint4*)&Bl[off] = lo;
        }
        __syncthreads();
        #pragma unroll
        for (int pass = 0; pass < 3; pass++) {
            uint32_t aB = (pass == 2) ? alB : ahB;
            uint32_t bB = (pass == 1) ? blB : bhB;
            #pragma unroll
            for (int ks = 0; ks < 2; ks++) {
                uint32_t afr[2][4], bfr[2][4];
                #pragma unroll
                for (int mt = 0; mt < 2; mt++)
                    ldsm4(afr[mt], aB + soff(arow + mt*16, ag + ks*2)*2);
                #pragma unroll
                for (int nb2 = 0; nb2 < 2; nb2++)
                    ldsm4(bfr[nb2], bB + soff(brow + nb2*16, bg + ks*2)*2);
                #pragma unroll
                for (int mt = 0; mt < 2; mt++) {
                    mma16816(d[mt][0], afr[mt], bfr[0][0], bfr[0][1]);
                    mma16816(d[mt][1], afr[mt], bfr[0][2], bfr[0][3]);
                    mma16816(d[mt][2], afr[mt], bfr[1][0], bfr[1][1]);
                    mma16816(d[mt][3], afr[mt], bfr[1][2], bfr[1][3]);
                }
            }
        }
        __syncthreads();
    }

    int r0 = bm + wm + (lane >> 2);
    int c0 = bn + wn + (lane & 3)*2;
    #pragma unroll
    for (int mt = 0; mt < 2; mt++) {
        #pragma unroll
        for (int nt = 0; nt < 4; nt++) {
            int row = r0 + mt*16, col = c0 + nt*8;
            float2 bs = *(const float2*)&bias[col];
            *(float2*)&C[(size_t)row*ldc + col] =
                make_float2(d[mt][nt][0] + bs.x, d[mt][nt][1] + bs.y);
            *(float2*)&C[(size_t)(row + 8)*ldc + col] =
                make_float2(d[mt][nt][2] + bs.x, d[mt][nt][3] + bs.y);
        }
    }
}

// ---------------- LayerNorm / activation ----------------
#define F_LN       1
#define F_POSTRELU 2
#define F_RES      4
#define F_PRERELU  8

__global__ __launch_bounds__(256) void k_ln(
    const float* __restrict__ x, const float* __restrict__ g, const float* __restrict__ b,
    const float* __restrict__ res, float* __restrict__ out, int W, int flags)
{
    __shared__ float rs[8], rq[8];
    __shared__ float s_mean, s_rstd;
    int row = blockIdx.x, t = threadIdx.x;
    const float* xr = x + (size_t)row*W;
    int two = (W == 512);
    float v0 = xr[t];
    float v1 = two ? xr[t + 256] : 0.f;
    if (flags & F_PRERELU) { v0 = fmaxf(v0, 0.f); v1 = fmaxf(v1, 0.f); }
    float s = v0 + v1, sq = v0*v0 + v1*v1;
    #pragma unroll
    for (int o = 16; o > 0; o >>= 1) {
        s  += __shfl_xor_sync(0xffffffff, s,  o);
        sq += __shfl_xor_sync(0xffffffff, sq, o);
    }
    int warp = t >> 5, lane = t & 31;
    if (lane == 0) { rs[warp] = s; rq[warp] = sq; }
    __syncthreads();
    if (t == 0) {
        float S = 0.f, Q = 0.f;
        #pragma unroll
        for (int w = 0; w < 8; w++) { S += rs[w]; Q += rq[w]; }
        float mean = S / (float)W;
        float var = fmaxf(Q / (float)W - mean*mean, 0.f);
        s_mean = mean;
        s_rstd = rsqrtf(var + 1e-5f);
    }
    __syncthreads();
    float mean = s_mean, rstd = s_rstd;

    float val = v0;
    if (flags & F_LN)       val = (val - mean)*rstd*g[t] + b[t];
    if (flags & F_POSTRELU) val = fmaxf(val, 0.f);
    if (flags & F_RES)      val += res[(size_t)row*W + t];
    out[(size_t)row*W + t] = val;

    if (two) {
        int c = t + 256;
        float val2 = v1;
        if (flags & F_LN)       val2 = (val2 - mean)*rstd*g[c] + b[c];
        if (flags & F_POSTRELU) val2 = fmaxf(val2, 0.f);
        if (flags & F_RES)      val2 += res[(size_t)row*W + c];
        out[(size_t)row*W + c] = val2;
    }
}

// ---------------- Q/K/V -> bf16 hi/lo preprocessing ----------------
__global__ __launch_bounds__(256) void k_cvtqk(const float* __restrict__ qkv,
                                               __nv_bfloat16* __restrict__ qh,
                                               __nv_bfloat16* __restrict__ ql,
                                               __nv_bfloat16* __restrict__ kh,
                                               __nv_bfloat16* __restrict__ kl) {
    int idx = blockIdx.x*256 + threadIdx.x;        // 4096*1024
    int n = idx >> 10, c = idx & 1023;
    float v = qkv[(size_t)n*1536 + c];
    __nv_bfloat16 h = __float2bfloat16(v);
    __nv_bfloat16 l = __float2bfloat16(v - __bfloat162float(h));
    int hd = c & 511;
    size_t o = (size_t)(hd >> 7)*N_NODES*128 + (size_t)n*128 + (hd & 127);
    if (c < 512) { qh[o] = h; ql[o] = l; }
    else         { kh[o] = h; kl[o] = l; }
}

__global__ __launch_bounds__(256) void k_cvtv(const float* __restrict__ qkv,
                                              __nv_bfloat16* __restrict__ vh,
                                              __nv_bfloat16* __restrict__ vl) {
    __shared__ float tile[32][33];
    int nt = blockIdx.x*32, dt = blockIdx.y*32;
    int tx = threadIdx.x & 31, ty = threadIdx.x >> 5;
    #pragma unroll
    for (int i = 0; i < 4; i++)
        tile[ty + i*8][tx] = qkv[(size_t)(nt + ty + i*8)*1536 + 1024 + dt + tx];
    __syncthreads();
    #pragma unroll
    for (int i = 0; i < 4; i++) {
        int d = dt + ty + i*8;
        float v = tile[tx][ty + i*8];
        __nv_bfloat16 h = __float2bfloat16(v);
        __nv_bfloat16 l = __float2bfloat16(v - __bfloat162float(h));
        size_t o = (size_t)d*N_NODES + nt + tx;
        vh[o] = h; vl[o] = l;
    }
}

// ---------------- flash attention: split-bf16 HMMA ----------------
// BQ=128, BKV=64, 256 threads (8 warps: 4m x 2n), occ 1, grid (32,4).
// byte offsets in dynamic smem:
#define FL_QH 0
#define FL_QL 32768
#define FL_KH 65536
#define FL_KL 81920
#define FL_VH 98304
#define FL_VL 114688
#define FL_PH 131072
#define FL_PL 147456
#define FL_SS 163840
#define FL_ROW 198656
#define FL_TOTAL 200192
#define SSD 68

__device__ __forceinline__ uint32_t sofQb(int row, int g) {   // 128-bf16 rows
    return (uint32_t)(row*256 + ((g ^ (row & 7)) << 4));
}
__device__ __forceinline__ uint32_t sofVb(int row, int g) {   // 64-bf16 rows
    return (uint32_t)(row*128 + ((g ^ (row & 7)) << 4));
}

__global__ __launch_bounds__(256, 1) void k_flash(
    const __nv_bfloat16* __restrict__ qh, const __nv_bfloat16* __restrict__ ql,
    const __nv_bfloat16* __restrict__ kh, const __nv_bfloat16* __restrict__ kl,
    const __nv_bfloat16* __restrict__ vh, const __nv_bfloat16* __restrict__ vl,
    float* __restrict__ outp)
{
    extern __shared__ char smf[];
    float* Ss   = (float*)(smf + FL_SS);
    float* rowm = (float*)(smf + FL_ROW);
    float* rowl = rowm + 128;
    float* rowf = rowl + 128;

    int qb = blockIdx.x, head = blockIdx.y, t = threadIdx.x;
    int w = t >> 5, lane = t & 31;
    int n0 = qb*128, coff = head*128;
    int wm  = (w >> 1)*32;    // q base (32 rows per warp)
    int wn  = (w & 1)*32;     // S col base
    int wnd = (w & 1)*64;     // D col base

    uint32_t qhB = s2u(smf + FL_QH), qlB = s2u(smf + FL_QL);
    uint32_t khB = s2u(smf + FL_KH), klB = s2u(smf + FL_KL);
    uint32_t vhB = s2u(smf + FL_VH), vlB = s2u(smf + FL_VL);
    uint32_t phB = s2u(smf + FL_PH), plB = s2u(smf + FL_PL);

    // ---- load Q tiles (128 rows x 16 granules, 8/thread) ----
    const __nv_bfloat16* qhg = qh + ((size_t)head*N_NODES + n0)*128;
    const __nv_bfloat16* qlg = ql + ((size_t)head*N_NODES + n0)*128;
    #pragma unroll
    for (int l = 0; l < 8; l++) {
        int gid = t + l*256;
        int row = gid >> 4, g = gid & 15;
        uint32_t off = sofQb(row, g);
        *(uint4*)(smf + FL_QH + off) = *(const uint4*)(qhg + (size_t)row*128 + g*8);
        *(uint4*)(smf + FL_QL + off) = *(const uint4*)(qlg + (size_t)row*128 + g*8);
    }
    if (t < 128) { rowm[t] = -1e30f; rowl[t] = 0.f; }

    float oacc[2][8][4] = {};
    const float scale = 0.08838834764831845f;   // 1/sqrt(128)

    int arow = wm + (lane & 15);
    int ag   = lane >> 4;
    int browS = wn  + ((lane >> 4) << 3) + (lane & 7);
    int browD = wnd + ((lane >> 4) << 3) + (lane & 7);
    int bg   = (lane >> 3) & 1;

    const __nv_bfloat16* khg = kh + (size_t)head*N_NODES*128;
    const __nv_bfloat16* klg = kl + (size_t)head*N_NODES*128;
    const __nv_bfloat16* vhg = vh + (size_t)head*128*N_NODES;
    const __nv_bfloat16* vlg = vl + (size_t)head*128*N_NODES;

    for (int kb = 0; kb < 64; kb++) {
        __syncthreads();
        // ---- load K (64x16 granules) + V (128x8 granules), 4+4 per thread ----
        #pragma unroll
        for (int l = 0; l < 4; l++) {
            int gid = t + l*256;
            int row = gid >> 4, g = gid & 15;
            uint32_t off = sofQb(row, g);
            size_t so = (size_t)(kb*64 + row)*128 + g*8;
            *(uint4*)(smf + FL_KH + off) = *(const uint4*)(khg + so);
            *(uint4*)(smf + FL_KL + off) = *(const uint4*)(klg + so);
        }
        #pragma unroll
        for (int l = 0; l < 4; l++) {
            int gid = t + l*256;
            int row = gid >> 3, g = gid & 7;
            uint32_t off = sofVb(row, g);
            size_t so = (size_t)row*N_NODES + kb*64 + g*8;
            *(uint4*)(smf + FL_VH + off) = *(const uint4*)(vhg + so);
            *(uint4*)(smf + FL_VL + off) = *(const uint4*)(vlg + so);
        }
        __syncthreads();

        // ---- S = Q K^T (3 passes: QhKh, QhKl, QlKh) ----
        float sacc[2][4][4] = {};
        #pragma unroll
        for (int pass = 0; pass < 3; pass++) {
            uint32_t aB = (pass == 2) ? qlB : qhB;
            uint32_t bB = (pass == 1) ? klB : khB;
            #pragma unroll
            for (int ks = 0; ks < 8; ks++) {
                uint32_t afr[2][4], bfr[2][4];
                #pragma unroll
                for (int mt = 0; mt < 2; mt++)
                    ldsm4(afr[mt], aB + sofQb(arow + mt*16, ag + ks*2));
                #pragma unroll
                for (int nb = 0; nb < 2; nb++)
                    ldsm4(bfr[nb], bB + sofQb(browS + nb*16, bg + ks*2));
                #pragma unroll
                for (int mt = 0; mt < 2; mt++) {
                    mma16816(sacc[mt][0], afr[mt], bfr[0][0], bfr[0][1]);
                    mma16816(sacc[mt][1], afr[mt], bfr[0][2], bfr[0][3]);
                    mma16816(sacc[mt][2], afr[mt], bfr[1][0], bfr[1][1]);
                    mma16816(sacc[mt][3], afr[mt], bfr[1][2], bfr[1][3]);
                }
            }
        }
        // ---- store S (scaled) ----
        #pragma unroll
        for (int mt = 0; mt < 2; mt++) {
            int r = wm + mt*16 + (lane >> 2);
            #pragma unroll
            for (int nf = 0; nf < 4; nf++) {
                int c = wn + nf*8 + (lane & 3)*2;
                *(float2*)&Ss[r*SSD + c] =
                    make_float2(sacc[mt][nf][0]*scale, sacc[mt][nf][1]*scale);
                *(float2*)&Ss[(r + 8)*SSD + c] =
                    make_float2(sacc[mt][nf][2]*scale, sacc[mt][nf][3]*scale);
            }
        }
        __syncthreads();

        // ---- online softmax: 2 threads/row, 32 cols each; emit P bf16 hi/lo ----
        {
            int sr = t >> 1, cc = (t & 1)*32;
            float mold = rowm[sr];
            float mx = mold;
            float4 v[8];
            #pragma unroll
            for (int j = 0; j < 8; j++) {
                v[j] = *(float4*)&Ss[sr*SSD + cc + 4*j];
                mx = fmaxf(mx, fmaxf(fmaxf(v[j].x, v[j].y), fmaxf(v[j].z, v[j].w)));
            }
            mx = fmaxf(mx, __shfl_xor_sync(0xffffffffu, mx, 1));
            float ls = 0.f;
            #pragma unroll
            for (int g4 = 0; g4 < 4; g4++) {
                float e[8];
                #pragma unroll
                for (int j = 0; j < 4; j++) {
                    float* pv = &((float*)&v[g4*2])[j];
                    e[j] = __expf(*pv - mx);
                    e[4+j] = __expf(((float*)&v[g4*2+1])[j] - mx);
                }
                #pragma unroll
                for (int j = 0; j < 8; j++) ls += e[j];
                __nv_bfloat162 h0 = __float22bfloat162_rn(make_float2(e[0], e[1]));
                __nv_bfloat162 h1 = __float22bfloat162_rn(make_float2(e[2], e[3]));
                __nv_bfloat162 h2 = __float22bfloat162_rn(make_float2(e[4], e[5]));
                __nv_bfloat162 h3 = __float22bfloat162_rn(make_float2(e[6], e[7]));
                float2 f0 = __bfloat1622float2(h0), f1 = __bfloat1622float2(h1);
                float2 f2 = __bfloat1622float2(h2), f3 = __bfloat1622float2(h3);
                __nv_bfloat162 l0 = __float22bfloat162_rn(make_float2(e[0]-f0.x, e[1]-f0.y));
                __nv_bfloat162 l1 = __float22bfloat162_rn(make_float2(e[2]-f1.x, e[3]-f1.y));
                __nv_bfloat162 l2 = __float22bfloat162_rn(make_float2(e[4]-f2.x, e[5]-f2.y));
                __nv_bfloat162 l3 = __float22bfloat162_rn(make_float2(e[6]-f3.x, e[7]-f3.y));
                uint32_t off = sofVb(sr, (t & 1)*4 + g4);
                *(uint4*)(smf + FL_PH + off) =
                    make_uint4(*(uint32_t*)&h0, *(uint32_t*)&h1, *(uint32_t*)&h2, *(uint32_t*)&h3);
                *(uint4*)(smf + FL_PL + off) =
                    make_uint4(*(uint32_t*)&l0, *(uint32_t*)&l1, *(uint32_t*)&l2, *(uint32_t*)&l3);
            }
            ls += __shfl_xor_sync(0xffffffffu, ls, 1);
            if (!(t & 1)) {
                float f = __expf(mold - mx);
                rowl[sr] = rowl[sr]*f + ls;
                rowm[sr] = mx;
                rowf[sr] = f;
            }
        }
        __syncthreads();

        // ---- rescale O, then O += P V (3 passes: PhVh, PhVl, PlVh) ----
        #pragma unroll
        for (int mt = 0; mt < 2; mt++) {
            float f0 = rowf[wm + mt*16 + (lane >> 2)];
            float f1 = rowf[wm + mt*16 + 8 + (lane >> 2)];
            #pragma unroll
            for (int nf = 0; nf < 8; nf++) {
                oacc[mt][nf][0] *= f0; oacc[mt][nf][1] *= f0;
                oacc[mt][nf][2] *= f1; oacc[mt][nf][3] *= f1;
            }
        }
        #pragma unroll
        for (int pass = 0; pass < 3; pass++) {
            uint32_t aB = (pass == 2) ? plB : phB;
            uint32_t bB = (pass == 1) ? vlB : vhB;
            #pragma unroll
            for (int ks = 0; ks < 4; ks++) {
                uint32_t afr[2][4], bfr[4][4];
                #pragma unroll
                for (int mt = 0; mt < 2; mt++)
                    ldsm4(afr[mt], aB + sofVb(arow + mt*16, ag + ks*2));
                #pragma unroll
                for (int nb = 0; nb < 4; nb++)
                    ldsm4(bfr[nb], bB + sofVb(browD + nb*16, bg + ks*2));
                #pragma unroll
                for (int mt = 0; mt < 2; mt++)
                    #pragma unroll
                    for (int nf = 0; nf < 8; nf++)
                        mma16816(oacc[mt][nf], afr[mt],
                                 bfr[nf >> 1][(nf & 1)*2], bfr[nf >> 1][(nf & 1)*2 + 1]);
            }
        }
    }

    // ---- epilogue ----
    #pragma unroll
    for (int mt = 0; mt < 2; mt++) {
        int r = wm + mt*16 + (lane >> 2);
        float inv0 = 1.f / rowl[r];
        float inv1 = 1.f / rowl[r + 8];
        #pragma unroll
        for (int nf = 0; nf < 8; nf++) {
            int col = coff + wnd + nf*8 + (lane & 3)*2;
            *(float2*)&outp[(size_t)(n0 + r)*512 + col] =
                make_float2(oacc[mt][nf][0]*inv0, oacc[mt][nf][1]*inv0);
            *(float2*)&outp[(size_t)(n0 + r + 8)*512 + col] =
                make_float2(oacc[mt][nf][2]*inv1, oacc[mt][nf][3]*inv1);
        }
    }
}

// ---------------- launch ----------------
extern "C" void kernel_launch(void* const* d_in, const int* in_sizes, int n_in,
                              void* d_out, int out_size) {
    const float* x          = (const float*)d_in[0];
    const int*   ei         = (const int*)  d_in[1];
    const float* sage_wl    = (const float*)d_in[2];
    const float* sage_wr    = (const float*)d_in[3];
    const float* sage_bl    = (const float*)d_in[4];
    const float* ln_g       = (const float*)d_in[5];
    const float* ln_b       = (const float*)d_in[6];
    const float* conv_w     = (const float*)d_in[7];
    const float* conv_b     = (const float*)d_in[8];
    const float* cnorm_g    = (const float*)d_in[9];
    const float* cnorm_b    = (const float*)d_in[10];
    const float* in_proj_w  = (const float*)d_in[11];
    const float* in_proj_b  = (const float*)d_in[12];
    const float* out_proj_w = (const float*)d_in[13];
    const float* out_proj_b = (const float*)d_in[14];
    const float* anorm_g    = (const float*)d_in[15];
    const float* anorm_b    = (const float*)d_in[16];
    const float* fuse_w     = (const float*)d_in[17];
    const float* fuse_b     = (const float*)d_in[18];
    float* outp = (float*)d_out;

    float *ph, *pagg, *ptmp, *pca, *pcb, *pqkv, *pattn, *po, *po2;
    __nv_bfloat16 *pqh, *pql, *pkh, *pkl, *pvh, *pvl;
    cudaGetSymbolAddress((void**)&ph,    g_h);
    cudaGetSymbolAddress((void**)&pagg,  g_agg);
    cudaGetSymbolAddress((void**)&ptmp,  g_tmp);
    cudaGetSymbolAddress((void**)&pca,   g_ca);
    cudaGetSymbolAddress((void**)&pcb,   g_cb);
    cudaGetSymbolAddress((void**)&pqkv,  g_qkv);
    cudaGetSymbolAddress((void**)&pattn, g_attn);
    cudaGetSymbolAddress((void**)&po,    g_o);
    cudaGetSymbolAddress((void**)&po2,   g_o2);
    cudaGetSymbolAddress((void**)&pqh,   g_qh);
    cudaGetSymbolAddress((void**)&pql,   g_ql);
    cudaGetSymbolAddress((void**)&pkh,   g_kh);
    cudaGetSymbolAddress((void**)&pkl,   g_kl);
    cudaGetSymbolAddress((void**)&pvh,   g_vh);
    cudaGetSymbolAddress((void**)&pvl,   g_vl);

    cudaFuncSetAttribute(k_flash, cudaFuncAttributeMaxDynamicSharedMemorySize, FL_TOTAL);

    // CSR build
    k_zero<<<16, 256>>>();
    k_count<<<E_EDGES/256, 256>>>(ei + E_EDGES);
    k_scan<<<1, 1024>>>();
    k_fill<<<E_EDGES/256, 256>>>(ei, ei + E_EDGES);

    dim3 g_hh(4, 64);

    // ---- GNN: 6 SAGE layers (K=512: [agg|h] x [wl;wr]) ----
    const float* hcur = x;
    for (int i = 0; i < 6; i++) {
        k_agg<<<N_NODES, 256>>>(hcur, pagg);
        k_mma<<<g_hh, 128>>>(
            pagg, H, 0, hcur, H, 0, pagg, H, 0,
            sage_wl + (size_t)i*H*H, sage_wr + (size_t)i*H*H, sage_wl, H, 1,
            ptmp, H, N_NODES, 2*H, sage_bl + i*H);
        int flags = (i < 5) ? (F_LN | F_POSTRELU | F_RES) : (F_POSTRELU | F_RES);
        k_ln<<<N_NODES, 256>>>(ptmp, (i < 5) ? ln_g + i*H : nullptr,
                               (i < 5) ? ln_b + i*H : nullptr,
                               hcur, ph, H, flags);
        hcur = ph;
    }

    // ---- CNN branch ----
    const float* cin = ph;
    float* couts[3] = {pca, pcb, pca};
    for (int j = 0; j < 3; j++) {
        const float* wj = conv_w + (size_t)j*H*H*3;
        k_mma<<<g_hh, 128>>>(
            cin, H, -1, cin, H, 0, cin, H, 1,
            wj + 0, wj + 1, wj + 2, 3*H, 3,
            ptmp, H, N_NODES, 3*H, conv_b + j*H);
        k_ln<<<N_NODES, 256>>>(ptmp, cnorm_g + j*H, cnorm_b + j*H,
                               nullptr, couts[j], H, F_LN | F_PRERELU);
        cin = couts[j];
    }

    // ---- qkv projection ----
    dim3 g_qkvd(24, 64);
    k_mma<<<g_qkvd, 128>>>(
        ph, H, 0, cin, H, 0, ph, H, 0,
        in_proj_w, in_proj_w + 256, in_proj_w, 512, 1,
        pqkv, 1536, N_NODES, 512, in_proj_b);

    // ---- convert Q/K/V to bf16 hi/lo (V transposed) ----
    k_cvtqk<<<(N_NODES*1024)/256, 256>>>(pqkv, pqh, pql, pkh, pkl);
    dim3 g_cv(N_NODES/32, 16);
    k_cvtv<<<g_cv, 256>>>(pqkv, pvh, pvl);

    // ---- flash attention (HMMA) ----
    dim3 g_fl(32, 4);
    k_flash<<<g_fl, 256, FL_TOTAL>>>(pqh, pql, pkh, pkl, pvh, pvl, pattn);

    // ---- out_proj + LN + fuse ----
    dim3 g_op(8, 64);
    k_mma<<<g_op, 128>>>(
        pattn, 512, 0, pattn + 256, 512, 0, pattn, 512, 0,
        out_proj_w, out_proj_w + 256, out_proj_w, 512, 1,
        po, 512, N_NODES, 512, out_proj_b);
    k_ln<<<N_NODES, 256>>>(po, anorm_g, anorm_b, nullptr, po2, 512, F_LN);
    dim3 g_fu(1, 64);
    k_mma<<<g_fu, 128>>>(
        po2, 512, 0, po2 + 256, 512, 0, po2, 512, 0,
        fuse_w, fuse_w + 256, fuse_w, 512, 1,
        outp, 64, N_NODES, 512, fuse_b);
}

// round 13
// speedup vs baseline: 2.9758x; 1.2039x over previous
#include <cuda_runtime.h>
#include <cuda_bf16.h>
#include <math.h>
#include <stdint.h>

#define N_NODES 4096
#define H 256
#define E_EDGES 131072

typedef unsigned long long u64;

__device__ __forceinline__ uint32_t s2u(const void* p) {
    uint32_t a;
    asm("{ .reg .u64 t; cvta.to.shared.u64 t, %1; cvt.u32.u64 %0, t; }"
        : "=r"(a) : "l"(p));
    return a;
}
__device__ __forceinline__ void ldsm4(uint32_t (&r)[4], uint32_t addr) {
    asm volatile("ldmatrix.sync.aligned.m8n8.x4.shared.b16 {%0,%1,%2,%3}, [%4];"
                 : "=r"(r[0]), "=r"(r[1]), "=r"(r[2]), "=r"(r[3]) : "r"(addr));
}
__device__ __forceinline__ void mma16816(float (&d)[4], const uint32_t (&a)[4],
                                         uint32_t b0, uint32_t b1) {
    asm volatile(
        "mma.sync.aligned.m16n8k16.row.col.f32.bf16.bf16.f32 "
        "{%0,%1,%2,%3}, {%4,%5,%6,%7}, {%8,%9}, {%0,%1,%2,%3};"
        : "+f"(d[0]), "+f"(d[1]), "+f"(d[2]), "+f"(d[3])
        : "r"(a[0]), "r"(a[1]), "r"(a[2]), "r"(a[3]), "r"(b0), "r"(b1));
}
__device__ __forceinline__ void cpa16(uint32_t d, const void* s, bool ok) {
    int sz = ok ? 16 : 0;
    asm volatile("cp.async.cg.shared.global [%0], [%1], 16, %2;"
                 :: "r"(d), "l"(s), "r"(sz));
}
#define CP_COMMIT() asm volatile("cp.async.commit_group;" ::: "memory")
#define CP_WAIT(n)  asm volatile("cp.async.wait_group %0;" :: "n"(n) : "memory")
__device__ __forceinline__ uint32_t b2u(__nv_bfloat162 h) { return *(uint32_t*)&h; }

// ---------------- scratch ----------------
__device__ float g_h[N_NODES*H];
__device__ float g_tmp[N_NODES*H];
__device__ float g_qkv[N_NODES*6*H];
__device__ float g_o[N_NODES*2*H];
__device__ __nv_bfloat16 g_aggh[N_NODES*H], g_aggl[N_NODES*H];
__device__ __nv_bfloat16 g_hbh[N_NODES*H],  g_hbl[N_NODES*H];
__device__ __nv_bfloat16 g_cah[N_NODES*H],  g_cal[N_NODES*H];
__device__ __nv_bfloat16 g_cbh[N_NODES*H],  g_cbl[N_NODES*H];
__device__ __nv_bfloat16 g_atth[N_NODES*2*H], g_attl[N_NODES*2*H];
__device__ __nv_bfloat16 g_o2h[N_NODES*2*H],  g_o2l[N_NODES*2*H];
#define W_SAGE 0
#define W_CONV 786432
#define W_INP  1376256
#define W_OUTP 2162688
#define W_FUSE 2424832
#define W_TOT  2457600
__device__ __nv_bfloat16 g_wh[W_TOT], g_wl[W_TOT];
__device__ __nv_bfloat16 g_qh[4*N_NODES*128], g_ql[4*N_NODES*128];
__device__ __nv_bfloat16 g_kh[4*N_NODES*128], g_kl[4*N_NODES*128];
__device__ __nv_bfloat16 g_vh[512*N_NODES],   g_vl[512*N_NODES];
__device__ int   g_cnt[N_NODES];
__device__ int   g_fillp[N_NODES];
__device__ int   g_off[N_NODES+1];
__device__ int   g_csrs[E_EDGES];
__device__ float g_degf[N_NODES];

// ---------------- CSR build ----------------
__global__ void k_zero() {
    int i = blockIdx.x*256 + threadIdx.x;
    if (i < N_NODES) { g_cnt[i] = 0; g_fillp[i] = 0; }
}
__global__ void k_count(const int* __restrict__ dst) {
    int e = blockIdx.x*256 + threadIdx.x;
    if (e < E_EDGES) atomicAdd(&g_cnt[dst[e]], 1);
}
__global__ void k_scan() {
    __shared__ int ps[1024];
    int t = threadIdx.x;
    int c[4]; int s = 0;
    #pragma unroll
    for (int l = 0; l < 4; l++) { c[l] = g_cnt[t*4+l]; s += c[l]; }
    ps[t] = s;
    __syncthreads();
    for (int d = 1; d < 1024; d <<= 1) {
        int v = (t >= d) ? ps[t-d] : 0;
        __syncthreads();
        ps[t] += v;
        __syncthreads();
    }
    int base = ps[t] - s;
    #pragma unroll
    for (int l = 0; l < 4; l++) {
        g_off[t*4+l] = base;
        base += c[l];
        g_degf[t*4+l] = (float)max(c[l], 1);
    }
    if (t == 1023) g_off[N_NODES] = ps[1023];
}
__global__ void k_fill(const int* __restrict__ src, const int* __restrict__ dst) {
    int e = blockIdx.x*256 + threadIdx.x;
    if (e < E_EDGES) {
        int d = dst[e];
        int p = atomicAdd(&g_fillp[d], 1);
        g_csrs[g_off[d] + p] = src[e];
    }
}

// ---------------- weight packing (fp32 -> bf16 hi/lo, segmented gather) ----------------
__global__ __launch_bounds__(256) void k_packw(
    const float* __restrict__ s0, const float* __restrict__ s1,
    const float* __restrict__ s2, int rs, int es, int K, int total,
    __nv_bfloat16* __restrict__ dh, __nv_bfloat16* __restrict__ dl)
{
    int idx = blockIdx.x*256 + threadIdx.x;
    if (idx >= total) return;
    int r = idx / K, k = idx - r*K;
    int seg = k >> 8, kc = k & 255;
    const float* s = (seg == 0) ? s0 : (seg == 1) ? s1 : s2;
    float v = s[(size_t)r*rs + kc*es];
    __nv_bfloat16 h = __float2bfloat16(v);
    dh[idx] = h;
    dl[idx] = __float2bfloat16(v - __bfloat162float(h));
}

__global__ __launch_bounds__(256) void k_cvtx(const float* __restrict__ x,
                                              __nv_bfloat16* __restrict__ oh,
                                              __nv_bfloat16* __restrict__ ol) {
    int i = blockIdx.x*256 + threadIdx.x;
    float v = x[i];
    __nv_bfloat16 h = __float2bfloat16(v);
    oh[i] = h;
    ol[i] = __float2bfloat16(v - __bfloat162float(h));
}

// ---------------- mean aggregation -> bf16 hi/lo ----------------
__global__ __launch_bounds__(256) void k_agg(const float* __restrict__ h,
                                             __nv_bfloat16* __restrict__ aggh,
                                             __nv_bfloat16* __restrict__ aggl) {
    int n = blockIdx.x;
    int f = threadIdx.x;
    int s = g_off[n], e = g_off[n+1];
    __shared__ int nb[256];
    float acc = 0.f;
    for (int base = s; base < e; base += 256) {
        int m = min(256, e - base);
        if (f < m) nb[f] = g_csrs[base + f];
        __syncthreads();
        for (int j = 0; j < m; j++)
            acc += h[(size_t)nb[j]*H + f];
        __syncthreads();
    }
    float v = acc / g_degf[n];
    __nv_bfloat16 hi = __float2bfloat16(v);
    aggh[(size_t)n*H + f] = hi;
    aggl[(size_t)n*H + f] = __float2bfloat16(v - __bfloat162float(hi));
}

// ---------------- HMMA bf16 GEMM (all-bf16 in, cp.async double-buffered) ----------------
__device__ __forceinline__ uint32_t soff(int row, int g) {
    return (uint32_t)(row*32 + ((g ^ ((row >> 1) & 3)) << 3));
}

__global__ __launch_bounds__(128) void k_mma(
    const __nv_bfloat16* __restrict__ Ah0, const __nv_bfloat16* __restrict__ Al0, int ld0, int sh0,
    const __nv_bfloat16* __restrict__ Ah1, const __nv_bfloat16* __restrict__ Al1, int ld1, int sh1,
    const __nv_bfloat16* __restrict__ Ah2, const __nv_bfloat16* __restrict__ Al2, int ld2, int sh2,
    const __nv_bfloat16* __restrict__ Bh, const __nv_bfloat16* __restrict__ Bl, int ldb,
    float* __restrict__ C, int ldc, int M, int K,
    const float* __restrict__ bias)
{
    __shared__ __nv_bfloat16 SA[2][2][2048];   // [stage][hi/lo]
    __shared__ __nv_bfloat16 SB[2][2][2048];
    int t = threadIdx.x, w = t >> 5, lane = t & 31;
    int bm = blockIdx.y*64, bn = blockIdx.x*64;
    int wm = (w & 1)*32, wn = (w >> 1)*32;

    float d[2][4][4] = {};

    int arow = wm + (lane & 15);
    int ag   = lane >> 4;
    int brow = wn + ((lane >> 4) << 3) + (lane & 7);
    int bg   = (lane >> 3) & 1;

    auto issue = [&](int kb, int stg) {
        int k0 = kb << 5;
        int seg = k0 >> 8, kc = k0 & 255;
        const __nv_bfloat16* Ah = (seg == 0) ? Ah0 : (seg == 1) ? Ah1 : Ah2;
        const __nv_bfloat16* Al = (seg == 0) ? Al0 : (seg == 1) ? Al1 : Al2;
        int lda = (seg == 0) ? ld0 : (seg == 1) ? ld1 : ld2;
        int sh  = (seg == 0) ? sh0 : (seg == 1) ? sh1 : sh2;
        uint32_t aH = s2u(SA[stg][0]), aL = s2u(SA[stg][1]);
        uint32_t bH = s2u(SB[stg][0]), bL = s2u(SB[stg][1]);
        #pragma unroll
        for (int l = 0; l < 2; l++) {
            int row = (t + l*128) >> 2, g = t & 3;
            int gr = bm + row + sh;
            bool ok = (gr >= 0 && gr < M);
            size_t so = ok ? ((size_t)gr*lda + kc + g*8) : 0;
            uint32_t off = soff(row, g)*2;
            cpa16(aH + off, Ah + so, ok);
            cpa16(aL + off, Al + so, ok);
        }
        #pragma unroll
        for (int l = 0; l < 2; l++) {
            int row = (t + l*128) >> 2, g = t & 3;
            // B is the packed full-K-width array: column offset is k0, NOT kc.
            size_t so = (size_t)(bn + row)*ldb + k0 + g*8;
            uint32_t off = soff(row, g)*2;
            cpa16(bH + off, Bh + so, true);
            cpa16(bL + off, Bl + so, true);
        }
    };
    auto compute = [&](int stg) {
        uint32_t ahB = s2u(SA[stg][0]), alB = s2u(SA[stg][1]);
        uint32_t bhB = s2u(SB[stg][0]), blB = s2u(SB[stg][1]);
        #pragma unroll
        for (int pass = 0; pass < 3; pass++) {
            uint32_t aB = (pass == 2) ? alB : ahB;
            uint32_t bB = (pass == 1) ? blB : bhB;
            #pragma unroll
            for (int ks = 0; ks < 2; ks++) {
                uint32_t afr[2][4], bfr[2][4];
                #pragma unroll
                for (int mt = 0; mt < 2; mt++)
                    ldsm4(afr[mt], aB + soff(arow + mt*16, ag + ks*2)*2);
                #pragma unroll
                for (int nb2 = 0; nb2 < 2; nb2++)
                    ldsm4(bfr[nb2], bB + soff(brow + nb2*16, bg + ks*2)*2);
                #pragma unroll
                for (int mt = 0; mt < 2; mt++) {
                    mma16816(d[mt][0], afr[mt], bfr[0][0], bfr[0][1]);
                    mma16816(d[mt][1], afr[mt], bfr[0][2], bfr[0][3]);
                    mma16816(d[mt][2], afr[mt], bfr[1][0], bfr[1][1]);
                    mma16816(d[mt][3], afr[mt], bfr[1][2], bfr[1][3]);
                }
            }
        }
    };

    int nb = K >> 5;
    issue(0, 0); CP_COMMIT();
    int buf = 0;
    for (int kb = 0; kb < nb; kb++) {
        if (kb + 1 < nb) { issue(kb + 1, buf ^ 1); CP_COMMIT(); CP_WAIT(1); }
        else CP_WAIT(0);
        __syncthreads();
        compute(buf);
        __syncthreads();
        buf ^= 1;
    }

    int r0 = bm + wm + (lane >> 2);
    int c0 = bn + wn + (lane & 3)*2;
    #pragma unroll
    for (int mt = 0; mt < 2; mt++) {
        #pragma unroll
        for (int nt = 0; nt < 4; nt++) {
            int row = r0 + mt*16, col = c0 + nt*8;
            float2 bs = *(const float2*)&bias[col];
            *(float2*)&C[(size_t)row*ldc + col] =
                make_float2(d[mt][nt][0] + bs.x, d[mt][nt][1] + bs.y);
            *(float2*)&C[(size_t)(row + 8)*ldc + col] =
                make_float2(d[mt][nt][2] + bs.x, d[mt][nt][3] + bs.y);
        }
    }
}

// ---------------- LayerNorm / activation (+ bf16 hi/lo out) ----------------
#define F_LN       1
#define F_POSTRELU 2
#define F_RES      4
#define F_PRERELU  8

__global__ __launch_bounds__(256) void k_ln(
    const float* __restrict__ x, const float* __restrict__ g, const float* __restrict__ b,
    const float* __restrict__ res, float* __restrict__ out,
    __nv_bfloat16* __restrict__ oh, __nv_bfloat16* __restrict__ ol,
    int W, int flags)
{
    __shared__ float rs[8], rq[8];
    __shared__ float s_mean, s_rstd;
    int row = blockIdx.x, t = threadIdx.x;
    const float* xr = x + (size_t)row*W;
    int two = (W == 512);
    float v0 = xr[t];
    float v1 = two ? xr[t + 256] : 0.f;
    if (flags & F_PRERELU) { v0 = fmaxf(v0, 0.f); v1 = fmaxf(v1, 0.f); }
    float s = v0 + v1, sq = v0*v0 + v1*v1;
    #pragma unroll
    for (int o = 16; o > 0; o >>= 1) {
        s  += __shfl_xor_sync(0xffffffff, s,  o);
        sq += __shfl_xor_sync(0xffffffff, sq, o);
    }
    int warp = t >> 5, lane = t & 31;
    if (lane == 0) { rs[warp] = s; rq[warp] = sq; }
    __syncthreads();
    if (t == 0) {
        float S = 0.f, Q = 0.f;
        #pragma unroll
        for (int w = 0; w < 8; w++) { S += rs[w]; Q += rq[w]; }
        float mean = S / (float)W;
        float var = fmaxf(Q / (float)W - mean*mean, 0.f);
        s_mean = mean;
        s_rstd = rsqrtf(var + 1e-5f);
    }
    __syncthreads();
    float mean = s_mean, rstd = s_rstd;

    float val = v0;
    if (flags & F_LN)       val = (val - mean)*rstd*g[t] + b[t];
    if (flags & F_POSTRELU) val = fmaxf(val, 0.f);
    if (flags & F_RES)      val += res[(size_t)row*W + t];
    size_t idx = (size_t)row*W + t;
    if (out) out[idx] = val;
    __nv_bfloat16 hh = __float2bfloat16(val);
    oh[idx] = hh;
    ol[idx] = __float2bfloat16(val - __bfloat162float(hh));

    if (two) {
        int c = t + 256;
        float val2 = v1;
        if (flags & F_LN)       val2 = (val2 - mean)*rstd*g[c] + b[c];
        if (flags & F_POSTRELU) val2 = fmaxf(val2, 0.f);
        if (flags & F_RES)      val2 += res[(size_t)row*W + c];
        size_t idx2 = (size_t)row*W + c;
        if (out) out[idx2] = val2;
        __nv_bfloat16 hh2 = __float2bfloat16(val2);
        oh[idx2] = hh2;
        ol[idx2] = __float2bfloat16(val2 - __bfloat162float(hh2));
    }
}

// ---------------- Q/K/V -> bf16 hi/lo preprocessing ----------------
__global__ __launch_bounds__(256) void k_cvtqk(const float* __restrict__ qkv,
                                               __nv_bfloat16* __restrict__ qh,
                                               __nv_bfloat16* __restrict__ ql,
                                               __nv_bfloat16* __restrict__ kh,
                                               __nv_bfloat16* __restrict__ kl) {
    int idx = blockIdx.x*256 + threadIdx.x;        // 4096*1024
    int n = idx >> 10, c = idx & 1023;
    float v = qkv[(size_t)n*1536 + c];
    __nv_bfloat16 h = __float2bfloat16(v);
    __nv_bfloat16 l = __float2bfloat16(v - __bfloat162float(h));
    int hd = c & 511;
    size_t o = (size_t)(hd >> 7)*N_NODES*128 + (size_t)n*128 + (hd & 127);
    if (c < 512) { qh[o] = h; ql[o] = l; }
    else         { kh[o] = h; kl[o] = l; }
}

__global__ __launch_bounds__(256) void k_cvtv(const float* __restrict__ qkv,
                                              __nv_bfloat16* __restrict__ vh,
                                              __nv_bfloat16* __restrict__ vl) {
    __shared__ float tile[32][33];
    int nt = blockIdx.x*32, dt = blockIdx.y*32;
    int tx = threadIdx.x & 31, ty = threadIdx.x >> 5;
    #pragma unroll
    for (int i = 0; i < 4; i++)
        tile[ty + i*8][tx] = qkv[(size_t)(nt + ty + i*8)*1536 + 1024 + dt + tx];
    __syncthreads();
    #pragma unroll
    for (int i = 0; i < 4; i++) {
        int d = dt + ty + i*8;
        float v = tile[tx][ty + i*8];
        __nv_bfloat16 h = __float2bfloat16(v);
        __nv_bfloat16 l = __float2bfloat16(v - __bfloat162float(h));
        size_t o = (size_t)d*N_NODES + nt + tx;
        vh[o] = h; vl[o] = l;
    }
}

// ---------------- flash attention: split-bf16 HMMA (cp.async overlapped) ----------------
#define FL_QH 0
#define FL_QL 32768
#define FL_KH 65536
#define FL_KL 81920
#define FL_VH 98304
#define FL_VL 114688
#define FL_PH 131072
#define FL_PL 147456
#define FL_SS 163840
#define FL_ROW 198656
#define FL_TOTAL 200192
#define SSD 68

__device__ __forceinline__ uint32_t sofQb(int row, int g) {
    return (uint32_t)(row*256 + ((g ^ (row & 7)) << 4));
}
__device__ __forceinline__ uint32_t sofVb(int row, int g) {
    return (uint32_t)(row*128 + ((g ^ (row & 7)) << 4));
}

__global__ __launch_bounds__(256, 1) void k_flash(
    const __nv_bfloat16* __restrict__ qh, const __nv_bfloat16* __restrict__ ql,
    const __nv_bfloat16* __restrict__ kh, const __nv_bfloat16* __restrict__ kl,
    const __nv_bfloat16* __restrict__ vh, const __nv_bfloat16* __restrict__ vl,
    __nv_bfloat16* __restrict__ atth, __nv_bfloat16* __restrict__ attl)
{
    extern __shared__ char smf[];
    float* Ss   = (float*)(smf + FL_SS);
    float* rowm = (float*)(smf + FL_ROW);
    float* rowl = rowm + 128;
    float* rowf = rowl + 128;

    int qb = blockIdx.x, head = blockIdx.y, t = threadIdx.x;
    int w = t >> 5, lane = t & 31;
    int n0 = qb*128, coff = head*128;
    int wm  = (w >> 1)*32;
    int wn  = (w & 1)*32;
    int wnd = (w & 1)*64;

    uint32_t qhB = s2u(smf + FL_QH), qlB = s2u(smf + FL_QL);
    uint32_t khB = s2u(smf + FL_KH), klB = s2u(smf + FL_KL);
    uint32_t vhB = s2u(smf + FL_VH), vlB = s2u(smf + FL_VL);
    uint32_t phB = s2u(smf + FL_PH), plB = s2u(smf + FL_PL);

    const __nv_bfloat16* qhg = qh + ((size_t)head*N_NODES + n0)*128;
    const __nv_bfloat16* qlg = ql + ((size_t)head*N_NODES + n0)*128;
    #pragma unroll
    for (int l = 0; l < 8; l++) {
        int gid = t + l*256;
        int row = gid >> 4, g = gid & 15;
        uint32_t off = sofQb(row, g);
        *(uint4*)(smf + FL_QH + off) = *(const uint4*)(qhg + (size_t)row*128 + g*8);
        *(uint4*)(smf + FL_QL + off) = *(const uint4*)(qlg + (size_t)row*128 + g*8);
    }
    if (t < 128) { rowm[t] = -1e30f; rowl[t] = 0.f; }

    float oacc[2][8][4] = {};
    const float scale = 0.08838834764831845f;

    int arow = wm + (lane & 15);
    int ag   = lane >> 4;
    int browS = wn  + ((lane >> 4) << 3) + (lane & 7);
    int browD = wnd + ((lane >> 4) << 3) + (lane & 7);
    int bg   = (lane >> 3) & 1;

    const __nv_bfloat16* khg = kh + (size_t)head*N_NODES*128;
    const __nv_bfloat16* klg = kl + (size_t)head*N_NODES*128;
    const __nv_bfloat16* vhg = vh + (size_t)head*128*N_NODES;
    const __nv_bfloat16* vlg = vl + (size_t)head*128*N_NODES;

    for (int kb = 0; kb < 64; kb++) {
        __syncthreads();
        // ---- issue K loads (group 1) ----
        #pragma unroll
        for (int l = 0; l < 4; l++) {
            int gid = t + l*256;
            int row = gid >> 4, g = gid & 15;
            uint32_t off = sofQb(row, g);
            size_t so = (size_t)(kb*64 + row)*128 + g*8;
            cpa16(khB + off, khg + so, true);
            cpa16(klB + off, klg + so, true);
        }
        CP_COMMIT();
        // ---- issue V loads (group 2) ----
        #pragma unroll
        for (int l = 0; l < 4; l++) {
            int gid = t + l*256;
            int row = gid >> 3, g = gid & 7;
            uint32_t off = sofVb(row, g);
            size_t so = (size_t)row*N_NODES + kb*64 + g*8;
            cpa16(vhB + off, vhg + so, true);
            cpa16(vlB + off, vlg + so, true);
        }
        CP_COMMIT();
        CP_WAIT(1);        // K ready; V in flight
        __syncthreads();

        // ---- S = Q K^T ----
        float sacc[2][4][4] = {};
        #pragma unroll
        for (int pass = 0; pass < 3; pass++) {
            uint32_t aB = (pass == 2) ? qlB : qhB;
            uint32_t bB = (pass == 1) ? klB : khB;
            #pragma unroll
            for (int ks = 0; ks < 8; ks++) {
                uint32_t afr[2][4], bfr[2][4];
                #pragma unroll
                for (int mt = 0; mt < 2; mt++)
                    ldsm4(afr[mt], aB + sofQb(arow + mt*16, ag + ks*2));
                #pragma unroll
                for (int nb = 0; nb < 2; nb++)
                    ldsm4(bfr[nb], bB + sofQb(browS + nb*16, bg + ks*2));
                #pragma unroll
                for (int mt = 0; mt < 2; mt++) {
                    mma16816(sacc[mt][0], afr[mt], bfr[0][0], bfr[0][1]);
                    mma16816(sacc[mt][1], afr[mt], bfr[0][2], bfr[0][3]);
                    mma16816(sacc[mt][2], afr[mt], bfr[1][0], bfr[1][1]);
                    mma16816(sacc[mt][3], afr[mt], bfr[1][2], bfr[1][3]);
                }
            }
        }
        #pragma unroll
        for (int mt = 0; mt < 2; mt++) {
            int r = wm + mt*16 + (lane >> 2);
            #pragma unroll
            for (int nf = 0; nf < 4; nf++) {
                int c = wn + nf*8 + (lane & 3)*2;
                *(float2*)&Ss[r*SSD + c] =
                    make_float2(sacc[mt][nf][0]*scale, sacc[mt][nf][1]*scale);
                *(float2*)&Ss[(r + 8)*SSD + c] =
                    make_float2(sacc[mt][nf][2]*scale, sacc[mt][nf][3]*scale);
            }
        }
        __syncthreads();

        // ---- online softmax; emit P bf16 hi/lo ----
        {
            int sr = t >> 1, cc = (t & 1)*32;
            float mold = rowm[sr];
            float mx = mold;
            float4 v[8];
            #pragma unroll
            for (int j = 0; j < 8; j++) {
                v[j] = *(float4*)&Ss[sr*SSD + cc + 4*j];
                mx = fmaxf(mx, fmaxf(fmaxf(v[j].x, v[j].y), fmaxf(v[j].z, v[j].w)));
            }
            mx = fmaxf(mx, __shfl_xor_sync(0xffffffffu, mx, 1));
            float ls = 0.f;
            #pragma unroll
            for (int g4 = 0; g4 < 4; g4++) {
                float e[8];
                #pragma unroll
                for (int j = 0; j < 4; j++) {
                    e[j]   = __expf(((float*)&v[g4*2])[j] - mx);
                    e[4+j] = __expf(((float*)&v[g4*2+1])[j] - mx);
                }
                #pragma unroll
                for (int j = 0; j < 8; j++) ls += e[j];
                __nv_bfloat162 h0 = __float22bfloat162_rn(make_float2(e[0], e[1]));
                __nv_bfloat162 h1 = __float22bfloat162_rn(make_float2(e[2], e[3]));
                __nv_bfloat162 h2 = __float22bfloat162_rn(make_float2(e[4], e[5]));
                __nv_bfloat162 h3 = __float22bfloat162_rn(make_float2(e[6], e[7]));
                float2 f0 = __bfloat1622float2(h0), f1 = __bfloat1622float2(h1);
                float2 f2 = __bfloat1622float2(h2), f3 = __bfloat1622float2(h3);
                __nv_bfloat162 l0 = __float22bfloat162_rn(make_float2(e[0]-f0.x, e[1]-f0.y));
                __nv_bfloat162 l1 = __float22bfloat162_rn(make_float2(e[2]-f1.x, e[3]-f1.y));
                __nv_bfloat162 l2 = __float22bfloat162_rn(make_float2(e[4]-f2.x, e[5]-f2.y));
                __nv_bfloat162 l3 = __float22bfloat162_rn(make_float2(e[6]-f3.x, e[7]-f3.y));
                uint32_t off = sofVb(sr, (t & 1)*4 + g4);
                *(uint4*)(smf + FL_PH + off) =
                    make_uint4(b2u(h0), b2u(h1), b2u(h2), b2u(h3));
                *(uint4*)(smf + FL_PL + off) =
                    make_uint4(b2u(l0), b2u(l1), b2u(l2), b2u(l3));
            }
            ls += __shfl_xor_sync(0xffffffffu, ls, 1);
            if (!(t & 1)) {
                float f = __expf(mold - mx);
                rowl[sr] = rowl[sr]*f + ls;
                rowm[sr] = mx;
                rowf[sr] = f;
            }
        }
        CP_WAIT(0);        // V arrived (hidden under QK + softmax)
        __syncthreads();

        // ---- rescale O, then O += P V ----
        #pragma unroll
        for (int mt = 0; mt < 2; mt++) {
            float f0 = rowf[wm + mt*16 + (lane >> 2)];
            float f1 = rowf[wm + mt*16 + 8 + (lane >> 2)];
            #pragma unroll
            for (int nf = 0; nf < 8; nf++) {
                oacc[mt][nf][0] *= f0; oacc[mt][nf][1] *= f0;
                oacc[mt][nf][2] *= f1; oacc[mt][nf][3] *= f1;
            }
        }
        #pragma unroll
        for (int pass = 0; pass < 3; pass++) {
            uint32_t aB = (pass == 2) ? plB : phB;
            uint32_t bB = (pass == 1) ? vlB : vhB;
            #pragma unroll
            for (int ks = 0; ks < 4; ks++) {
                uint32_t afr[2][4], bfr[4][4];
                #pragma unroll
                for (int mt = 0; mt < 2; mt++)
                    ldsm4(afr[mt], aB + sofVb(arow + mt*16, ag + ks*2));
                #pragma unroll
                for (int nb = 0; nb < 4; nb++)
                    ldsm4(bfr[nb], bB + sofVb(browD + nb*16, bg + ks*2));
                #pragma unroll
                for (int mt = 0; mt < 2; mt++)
                    #pragma unroll
                    for (int nf = 0; nf < 8; nf++)
                        mma16816(oacc[mt][nf], afr[mt],
                                 bfr[nf >> 1][(nf & 1)*2], bfr[nf >> 1][(nf & 1)*2 + 1]);
            }
        }
    }

    // ---- epilogue: bf16 hi/lo attn ----
    #pragma unroll
    for (int mt = 0; mt < 2; mt++) {
        int r = wm + mt*16 + (lane >> 2);
        float inv0 = 1.f / rowl[r];
        float inv1 = 1.f / rowl[r + 8];
        #pragma unroll
        for (int nf = 0; nf < 8; nf++) {
            int col = coff + wnd + nf*8 + (lane & 3)*2;
            float a0 = oacc[mt][nf][0]*inv0, a1 = oacc[mt][nf][1]*inv0;
            float a2 = oacc[mt][nf][2]*inv1, a3 = oacc[mt][nf][3]*inv1;
            __nv_bfloat162 h01 = __float22bfloat162_rn(make_float2(a0, a1));
            float2 f01 = __bfloat1622float2(h01);
            __nv_bfloat162 l01 = __float22bfloat162_rn(make_float2(a0 - f01.x, a1 - f01.y));
            __nv_bfloat162 h23 = __float22bfloat162_rn(make_float2(a2, a3));
            float2 f23 = __bfloat1622float2(h23);
            __nv_bfloat162 l23 = __float22bfloat162_rn(make_float2(a2 - f23.x, a3 - f23.y));
            *(uint32_t*)&atth[(size_t)(n0 + r)*512 + col] = b2u(h01);
            *(uint32_t*)&attl[(size_t)(n0 + r)*512 + col] = b2u(l01);
            *(uint32_t*)&atth[(size_t)(n0 + r + 8)*512 + col] = b2u(h23);
            *(uint32_t*)&attl[(size_t)(n0 + r + 8)*512 + col] = b2u(l23);
        }
    }
}

// ---------------- launch ----------------
extern "C" void kernel_launch(void* const* d_in, const int* in_sizes, int n_in,
                              void* d_out, int out_size) {
    const float* x          = (const float*)d_in[0];
    const int*   ei         = (const int*)  d_in[1];
    const float* sage_wl    = (const float*)d_in[2];
    const float* sage_wr    = (const float*)d_in[3];
    const float* sage_bl    = (const float*)d_in[4];
    const float* ln_g       = (const float*)d_in[5];
    const float* ln_b       = (const float*)d_in[6];
    const float* conv_w     = (const float*)d_in[7];
    const float* conv_b     = (const float*)d_in[8];
    const float* cnorm_g    = (const float*)d_in[9];
    const float* cnorm_b    = (const float*)d_in[10];
    const float* in_proj_w  = (const float*)d_in[11];
    const float* in_proj_b  = (const float*)d_in[12];
    const float* out_proj_w = (const float*)d_in[13];
    const float* out_proj_b = (const float*)d_in[14];
    const float* anorm_g    = (const float*)d_in[15];
    const float* anorm_b    = (const float*)d_in[16];
    const float* fuse_w     = (const float*)d_in[17];
    const float* fuse_b     = (const float*)d_in[18];
    float* outp = (float*)d_out;

    float *ph, *ptmp, *pqkv, *po;
    __nv_bfloat16 *paggh, *paggl, *phbh, *phbl, *pcah, *pcal, *pcbh, *pcbl;
    __nv_bfloat16 *patth, *pattl, *po2h, *po2l, *pwh, *pwl;
    __nv_bfloat16 *pqh, *pql, *pkh, *pkl, *pvh, *pvl;
    cudaGetSymbolAddress((void**)&ph,    g_h);
    cudaGetSymbolAddress((void**)&ptmp,  g_tmp);
    cudaGetSymbolAddress((void**)&pqkv,  g_qkv);
    cudaGetSymbolAddress((void**)&po,    g_o);
    cudaGetSymbolAddress((void**)&paggh, g_aggh);
    cudaGetSymbolAddress((void**)&paggl, g_aggl);
    cudaGetSymbolAddress((void**)&phbh,  g_hbh);
    cudaGetSymbolAddress((void**)&phbl,  g_hbl);
    cudaGetSymbolAddress((void**)&pcah,  g_cah);
    cudaGetSymbolAddress((void**)&pcal,  g_cal);
    cudaGetSymbolAddress((void**)&pcbh,  g_cbh);
    cudaGetSymbolAddress((void**)&pcbl,  g_cbl);
    cudaGetSymbolAddress((void**)&patth, g_atth);
    cudaGetSymbolAddress((void**)&pattl, g_attl);
    cudaGetSymbolAddress((void**)&po2h,  g_o2h);
    cudaGetSymbolAddress((void**)&po2l,  g_o2l);
    cudaGetSymbolAddress((void**)&pwh,   g_wh);
    cudaGetSymbolAddress((void**)&pwl,   g_wl);
    cudaGetSymbolAddress((void**)&pqh,   g_qh);
    cudaGetSymbolAddress((void**)&pql,   g_ql);
    cudaGetSymbolAddress((void**)&pkh,   g_kh);
    cudaGetSymbolAddress((void**)&pkl,   g_kl);
    cudaGetSymbolAddress((void**)&pvh,   g_vh);
    cudaGetSymbolAddress((void**)&pvl,   g_vl);

    cudaFuncSetAttribute(k_flash, cudaFuncAttributeMaxDynamicSharedMemorySize, FL_TOTAL);

    // CSR build + weight packing + x convert
    k_zero<<<16, 256>>>();
    k_count<<<E_EDGES/256, 256>>>(ei + E_EDGES);
    k_scan<<<1, 1024>>>();
    k_fill<<<E_EDGES/256, 256>>>(ei, ei + E_EDGES);
    k_packw<<<(1536*512+255)/256, 256>>>(sage_wl, sage_wr, sage_wl, 256, 1, 512,
                                         1536*512, pwh + W_SAGE, pwl + W_SAGE);
    k_packw<<<(768*768+255)/256, 256>>>(conv_w, conv_w + 1, conv_w + 2, 768, 3, 768,
                                        768*768, pwh + W_CONV, pwl + W_CONV);
    k_packw<<<(1536*512+255)/256, 256>>>(in_proj_w, in_proj_w + 256, in_proj_w, 512, 1, 512,
                                         1536*512, pwh + W_INP, pwl + W_INP);
    k_packw<<<(512*512+255)/256, 256>>>(out_proj_w, out_proj_w + 256, out_proj_w, 512, 1, 512,
                                        512*512, pwh + W_OUTP, pwl + W_OUTP);
    k_packw<<<(64*512+255)/256, 256>>>(fuse_w, fuse_w + 256, fuse_w, 512, 1, 512,
                                       64*512, pwh + W_FUSE, pwl + W_FUSE);
    k_cvtx<<<N_NODES*H/256, 256>>>(x, phbh, phbl);

    dim3 g_hh(4, 64);

    // ---- GNN: 6 SAGE layers ----
    const float* hcur = x;
    for (int i = 0; i < 6; i++) {
        k_agg<<<N_NODES, 256>>>(hcur, paggh, paggl);
        k_mma<<<g_hh, 128>>>(
            paggh, paggl, H, 0, phbh, phbl, H, 0, paggh, paggl, H, 0,
            pwh + W_SAGE + (size_t)i*H*512, pwl + W_SAGE + (size_t)i*H*512, 512,
            ptmp, H, N_NODES, 2*H, sage_bl + i*H);
        int flags = (i < 5) ? (F_LN | F_POSTRELU | F_RES) : (F_POSTRELU | F_RES);
        k_ln<<<N_NODES, 256>>>(ptmp, (i < 5) ? ln_g + i*H : nullptr,
                               (i < 5) ? ln_b + i*H : nullptr,
                               hcur, ph, phbh, phbl, H, flags);
        hcur = ph;
    }

    // ---- CNN branch ----
    __nv_bfloat16 *cinh = phbh, *cinl = phbl;
    __nv_bfloat16* ch[3] = {pcah, pcbh, pcah};
    __nv_bfloat16* cl[3] = {pcal, pcbl, pcal};
    for (int j = 0; j < 3; j++) {
        k_mma<<<g_hh, 128>>>(
            cinh, cinl, H, -1, cinh, cinl, H, 0, cinh, cinl, H, 1,
            pwh + W_CONV + (size_t)j*H*768, pwl + W_CONV + (size_t)j*H*768, 768,
            ptmp, H, N_NODES, 3*H, conv_b + j*H);
        k_ln<<<N_NODES, 256>>>(ptmp, cnorm_g + j*H, cnorm_b + j*H,
                               nullptr, nullptr, ch[j], cl[j], H, F_LN | F_PRERELU);
        cinh = ch[j]; cinl = cl[j];
    }

    // ---- qkv projection ----
    dim3 g_qkvd(24, 64);
    k_mma<<<g_qkvd, 128>>>(
        phbh, phbl, H, 0, cinh, cinl, H, 0, phbh, phbl, H, 0,
        pwh + W_INP, pwl + W_INP, 512,
        pqkv, 1536, N_NODES, 512, in_proj_b);

    // ---- convert Q/K/V ----
    k_cvtqk<<<(N_NODES*1024)/256, 256>>>(pqkv, pqh, pql, pkh, pkl);
    dim3 g_cv(N_NODES/32, 16);
    k_cvtv<<<g_cv, 256>>>(pqkv, pvh, pvl);

    // ---- flash attention ----
    dim3 g_fl(32, 4);
    k_flash<<<g_fl, 256, FL_TOTAL>>>(pqh, pql, pkh, pkl, pvh, pvl, patth, pattl);

    // ---- out_proj + LN + fuse ----
    dim3 g_op(8, 64);
    k_mma<<<g_op, 128>>>(
        patth, pattl, 512, 0, patth + 256, pattl + 256, 512, 0, patth, pattl, 512, 0,
        pwh + W_OUTP, pwl + W_OUTP, 512,
        po, 512, N_NODES, 512, out_proj_b);
    k_ln<<<N_NODES, 256>>>(po, anorm_g, anorm_b, nullptr, nullptr, po2h, po2l, 512, F_LN);
    dim3 g_fu(1, 64);
    k_mma<<<g_fu, 128>>>(
        po2h, po2l, 512, 0, po2h + 256, po2l + 256, 512, 0, po2h, po2l, 512, 0,
        pwh + W_FUSE, pwl + W_FUSE, 512,
        outp, 64, N_NODES, 512, fuse_b);
}

// round 14
// speedup vs baseline: 3.2977x; 1.1082x over previous
#include <cuda_runtime.h>
#include <cuda_bf16.h>
#include <math.h>
#include <stdint.h>

#define N_NODES 4096
#define H 256
#define E_EDGES 131072

typedef unsigned long long u64;

__device__ __forceinline__ uint32_t s2u(const void* p) {
    uint32_t a;
    asm("{ .reg .u64 t; cvta.to.shared.u64 t, %1; cvt.u32.u64 %0, t; }"
        : "=r"(a) : "l"(p));
    return a;
}
__device__ __forceinline__ void ldsm4(uint32_t (&r)[4], uint32_t addr) {
    asm volatile("ldmatrix.sync.aligned.m8n8.x4.shared.b16 {%0,%1,%2,%3}, [%4];"
                 : "=r"(r[0]), "=r"(r[1]), "=r"(r[2]), "=r"(r[3]) : "r"(addr));
}
__device__ __forceinline__ void mma16816(float (&d)[4], const uint32_t (&a)[4],
                                         uint32_t b0, uint32_t b1) {
    asm volatile(
        "mma.sync.aligned.m16n8k16.row.col.f32.bf16.bf16.f32 "
        "{%0,%1,%2,%3}, {%4,%5,%6,%7}, {%8,%9}, {%0,%1,%2,%3};"
        : "+f"(d[0]), "+f"(d[1]), "+f"(d[2]), "+f"(d[3])
        : "r"(a[0]), "r"(a[1]), "r"(a[2]), "r"(a[3]), "r"(b0), "r"(b1));
}
__device__ __forceinline__ void cpa16(uint32_t d, const void* s, bool ok) {
    int sz = ok ? 16 : 0;
    asm volatile("cp.async.cg.shared.global [%0], [%1], 16, %2;"
                 :: "r"(d), "l"(s), "r"(sz));
}
#define CP_COMMIT() asm volatile("cp.async.commit_group;" ::: "memory")
#define CP_WAIT(n)  asm volatile("cp.async.wait_group %0;" :: "n"(n) : "memory")
__device__ __forceinline__ uint32_t b2u(__nv_bfloat162 h) { return *(uint32_t*)&h; }

// ---------------- scratch ----------------
__device__ float g_h[N_NODES*H];
__device__ float g_tmp[N_NODES*H];
__device__ float g_qkv[N_NODES*6*H];
__device__ float g_o[N_NODES*2*H];
__device__ __nv_bfloat16 g_aggh[N_NODES*H], g_aggl[N_NODES*H];
__device__ __nv_bfloat16 g_hbh[N_NODES*H],  g_hbl[N_NODES*H];
__device__ __nv_bfloat16 g_cah[N_NODES*H],  g_cal[N_NODES*H];
__device__ __nv_bfloat16 g_cbh[N_NODES*H],  g_cbl[N_NODES*H];
__device__ __nv_bfloat16 g_atth[N_NODES*2*H], g_attl[N_NODES*2*H];
__device__ __nv_bfloat16 g_o2h[N_NODES*2*H],  g_o2l[N_NODES*2*H];
#define W_SAGE 0
#define W_CONV 786432
#define W_INP  1376256
#define W_OUTP 2162688
#define W_FUSE 2424832
#define W_TOT  2457600
__device__ __nv_bfloat16 g_wh[W_TOT], g_wl[W_TOT];
__device__ __nv_bfloat16 g_qh[4*N_NODES*128], g_ql[4*N_NODES*128];
__device__ __nv_bfloat16 g_kh[4*N_NODES*128], g_kl[4*N_NODES*128];
__device__ __nv_bfloat16 g_vh[512*N_NODES],   g_vl[512*N_NODES];
__device__ int   g_cnt[N_NODES];
__device__ int   g_fillp[N_NODES];
__device__ int   g_off[N_NODES+1];
__device__ int   g_csrs[E_EDGES];
__device__ float g_degf[N_NODES];

// ---------------- CSR build ----------------
__global__ void k_zero() {
    int i = blockIdx.x*256 + threadIdx.x;
    if (i < N_NODES) { g_cnt[i] = 0; g_fillp[i] = 0; }
}
__global__ void k_count(const int* __restrict__ dst) {
    int e = blockIdx.x*256 + threadIdx.x;
    if (e < E_EDGES) atomicAdd(&g_cnt[dst[e]], 1);
}
__global__ void k_scan() {
    __shared__ int ps[1024];
    int t = threadIdx.x;
    int c[4]; int s = 0;
    #pragma unroll
    for (int l = 0; l < 4; l++) { c[l] = g_cnt[t*4+l]; s += c[l]; }
    ps[t] = s;
    __syncthreads();
    for (int d = 1; d < 1024; d <<= 1) {
        int v = (t >= d) ? ps[t-d] : 0;
        __syncthreads();
        ps[t] += v;
        __syncthreads();
    }
    int base = ps[t] - s;
    #pragma unroll
    for (int l = 0; l < 4; l++) {
        g_off[t*4+l] = base;
        base += c[l];
        g_degf[t*4+l] = (float)max(c[l], 1);
    }
    if (t == 1023) g_off[N_NODES] = ps[1023];
}
__global__ void k_fill(const int* __restrict__ src, const int* __restrict__ dst) {
    int e = blockIdx.x*256 + threadIdx.x;
    if (e < E_EDGES) {
        int d = dst[e];
        int p = atomicAdd(&g_fillp[d], 1);
        g_csrs[g_off[d] + p] = src[e];
    }
}

// ---------------- weight packing ----------------
__global__ __launch_bounds__(256) void k_packw(
    const float* __restrict__ s0, const float* __restrict__ s1,
    const float* __restrict__ s2, int rs, int es, int K, int total,
    __nv_bfloat16* __restrict__ dh, __nv_bfloat16* __restrict__ dl)
{
    int idx = blockIdx.x*256 + threadIdx.x;
    if (idx >= total) return;
    int r = idx / K, k = idx - r*K;
    int seg = k >> 8, kc = k & 255;
    const float* s = (seg == 0) ? s0 : (seg == 1) ? s1 : s2;
    float v = s[(size_t)r*rs + kc*es];
    __nv_bfloat16 h = __float2bfloat16(v);
    dh[idx] = h;
    dl[idx] = __float2bfloat16(v - __bfloat162float(h));
}

__global__ __launch_bounds__(256) void k_cvtx(const float* __restrict__ x,
                                              __nv_bfloat16* __restrict__ oh,
                                              __nv_bfloat16* __restrict__ ol) {
    int i = blockIdx.x*256 + threadIdx.x;
    float v = x[i];
    __nv_bfloat16 h = __float2bfloat16(v);
    oh[i] = h;
    ol[i] = __float2bfloat16(v - __bfloat162float(h));
}

// ---------------- mean aggregation -> bf16 hi/lo ----------------
__global__ __launch_bounds__(256) void k_agg(const float* __restrict__ h,
                                             __nv_bfloat16* __restrict__ aggh,
                                             __nv_bfloat16* __restrict__ aggl) {
    int n = blockIdx.x;
    int f = threadIdx.x;
    int s = g_off[n], e = g_off[n+1];
    __shared__ int nb[256];
    float acc = 0.f;
    for (int base = s; base < e; base += 256) {
        int m = min(256, e - base);
        if (f < m) nb[f] = g_csrs[base + f];
        __syncthreads();
        for (int j = 0; j < m; j++)
            acc += h[(size_t)nb[j]*H + f];
        __syncthreads();
    }
    float v = acc / g_degf[n];
    __nv_bfloat16 hi = __float2bfloat16(v);
    aggh[(size_t)n*H + f] = hi;
    aggl[(size_t)n*H + f] = __float2bfloat16(v - __bfloat162float(hi));
}

// ---------------- HMMA bf16 GEMM (round-13, unchanged) ----------------
__device__ __forceinline__ uint32_t soff(int row, int g) {
    return (uint32_t)(row*32 + ((g ^ ((row >> 1) & 3)) << 3));
}

__global__ __launch_bounds__(128) void k_mma(
    const __nv_bfloat16* __restrict__ Ah0, const __nv_bfloat16* __restrict__ Al0, int ld0, int sh0,
    const __nv_bfloat16* __restrict__ Ah1, const __nv_bfloat16* __restrict__ Al1, int ld1, int sh1,
    const __nv_bfloat16* __restrict__ Ah2, const __nv_bfloat16* __restrict__ Al2, int ld2, int sh2,
    const __nv_bfloat16* __restrict__ Bh, const __nv_bfloat16* __restrict__ Bl, int ldb,
    float* __restrict__ C, int ldc, int M, int K,
    const float* __restrict__ bias)
{
    __shared__ __nv_bfloat16 SA[2][2][2048];
    __shared__ __nv_bfloat16 SB[2][2][2048];
    int t = threadIdx.x, w = t >> 5, lane = t & 31;
    int bm = blockIdx.y*64, bn = blockIdx.x*64;
    int wm = (w & 1)*32, wn = (w >> 1)*32;

    float d[2][4][4] = {};

    int arow = wm + (lane & 15);
    int ag   = lane >> 4;
    int brow = wn + ((lane >> 4) << 3) + (lane & 7);
    int bg   = (lane >> 3) & 1;

    auto issue = [&](int kb, int stg) {
        int k0 = kb << 5;
        int seg = k0 >> 8, kc = k0 & 255;
        const __nv_bfloat16* Ah = (seg == 0) ? Ah0 : (seg == 1) ? Ah1 : Ah2;
        const __nv_bfloat16* Al = (seg == 0) ? Al0 : (seg == 1) ? Al1 : Al2;
        int lda = (seg == 0) ? ld0 : (seg == 1) ? ld1 : ld2;
        int sh  = (seg == 0) ? sh0 : (seg == 1) ? sh1 : sh2;
        uint32_t aH = s2u(SA[stg][0]), aL = s2u(SA[stg][1]);
        uint32_t bH = s2u(SB[stg][0]), bL = s2u(SB[stg][1]);
        #pragma unroll
        for (int l = 0; l < 2; l++) {
            int row = (t + l*128) >> 2, g = t & 3;
            int gr = bm + row + sh;
            bool ok = (gr >= 0 && gr < M);
            size_t so = ok ? ((size_t)gr*lda + kc + g*8) : 0;
            uint32_t off = soff(row, g)*2;
            cpa16(aH + off, Ah + so, ok);
            cpa16(aL + off, Al + so, ok);
        }
        #pragma unroll
        for (int l = 0; l < 2; l++) {
            int row = (t + l*128) >> 2, g = t & 3;
            size_t so = (size_t)(bn + row)*ldb + k0 + g*8;
            uint32_t off = soff(row, g)*2;
            cpa16(bH + off, Bh + so, true);
            cpa16(bL + off, Bl + so, true);
        }
    };
    auto compute = [&](int stg) {
        uint32_t ahB = s2u(SA[stg][0]), alB = s2u(SA[stg][1]);
        uint32_t bhB = s2u(SB[stg][0]), blB = s2u(SB[stg][1]);
        #pragma unroll
        for (int pass = 0; pass < 3; pass++) {
            uint32_t aB = (pass == 2) ? alB : ahB;
            uint32_t bB = (pass == 1) ? blB : bhB;
            #pragma unroll
            for (int ks = 0; ks < 2; ks++) {
                uint32_t afr[2][4], bfr[2][4];
                #pragma unroll
                for (int mt = 0; mt < 2; mt++)
                    ldsm4(afr[mt], aB + soff(arow + mt*16, ag + ks*2)*2);
                #pragma unroll
                for (int nb2 = 0; nb2 < 2; nb2++)
                    ldsm4(bfr[nb2], bB + soff(brow + nb2*16, bg + ks*2)*2);
                #pragma unroll
                for (int mt = 0; mt < 2; mt++) {
                    mma16816(d[mt][0], afr[mt], bfr[0][0], bfr[0][1]);
                    mma16816(d[mt][1], afr[mt], bfr[0][2], bfr[0][3]);
                    mma16816(d[mt][2], afr[mt], bfr[1][0], bfr[1][1]);
                    mma16816(d[mt][3], afr[mt], bfr[1][2], bfr[1][3]);
                }
            }
        }
    };

    int nb = K >> 5;
    issue(0, 0); CP_COMMIT();
    int buf = 0;
    for (int kb = 0; kb < nb; kb++) {
        if (kb + 1 < nb) { issue(kb + 1, buf ^ 1); CP_COMMIT(); CP_WAIT(1); }
        else CP_WAIT(0);
        __syncthreads();
        compute(buf);
        __syncthreads();
        buf ^= 1;
    }

    int r0 = bm + wm + (lane >> 2);
    int c0 = bn + wn + (lane & 3)*2;
    #pragma unroll
    for (int mt = 0; mt < 2; mt++) {
        #pragma unroll
        for (int nt = 0; nt < 4; nt++) {
            int row = r0 + mt*16, col = c0 + nt*8;
            float2 bs = *(const float2*)&bias[col];
            *(float2*)&C[(size_t)row*ldc + col] =
                make_float2(d[mt][nt][0] + bs.x, d[mt][nt][1] + bs.y);
            *(float2*)&C[(size_t)(row + 8)*ldc + col] =
                make_float2(d[mt][nt][2] + bs.x, d[mt][nt][3] + bs.y);
        }
    }
}

// ---------------- LayerNorm / activation ----------------
#define F_LN       1
#define F_POSTRELU 2
#define F_RES      4
#define F_PRERELU  8

__global__ __launch_bounds__(256) void k_ln(
    const float* __restrict__ x, const float* __restrict__ g, const float* __restrict__ b,
    const float* __restrict__ res, float* __restrict__ out,
    __nv_bfloat16* __restrict__ oh, __nv_bfloat16* __restrict__ ol,
    int W, int flags)
{
    __shared__ float rs[8], rq[8];
    __shared__ float s_mean, s_rstd;
    int row = blockIdx.x, t = threadIdx.x;
    const float* xr = x + (size_t)row*W;
    int two = (W == 512);
    float v0 = xr[t];
    float v1 = two ? xr[t + 256] : 0.f;
    if (flags & F_PRERELU) { v0 = fmaxf(v0, 0.f); v1 = fmaxf(v1, 0.f); }
    float s = v0 + v1, sq = v0*v0 + v1*v1;
    #pragma unroll
    for (int o = 16; o > 0; o >>= 1) {
        s  += __shfl_xor_sync(0xffffffff, s,  o);
        sq += __shfl_xor_sync(0xffffffff, sq, o);
    }
    int warp = t >> 5, lane = t & 31;
    if (lane == 0) { rs[warp] = s; rq[warp] = sq; }
    __syncthreads();
    if (t == 0) {
        float S = 0.f, Q = 0.f;
        #pragma unroll
        for (int w = 0; w < 8; w++) { S += rs[w]; Q += rq[w]; }
        float mean = S / (float)W;
        float var = fmaxf(Q / (float)W - mean*mean, 0.f);
        s_mean = mean;
        s_rstd = rsqrtf(var + 1e-5f);
    }
    __syncthreads();
    float mean = s_mean, rstd = s_rstd;

    float val = v0;
    if (flags & F_LN)       val = (val - mean)*rstd*g[t] + b[t];
    if (flags & F_POSTRELU) val = fmaxf(val, 0.f);
    if (flags & F_RES)      val += res[(size_t)row*W + t];
    size_t idx = (size_t)row*W + t;
    if (out) out[idx] = val;
    __nv_bfloat16 hh = __float2bfloat16(val);
    oh[idx] = hh;
    ol[idx] = __float2bfloat16(val - __bfloat162float(hh));

    if (two) {
        int c = t + 256;
        float val2 = v1;
        if (flags & F_LN)       val2 = (val2 - mean)*rstd*g[c] + b[c];
        if (flags & F_POSTRELU) val2 = fmaxf(val2, 0.f);
        if (flags & F_RES)      val2 += res[(size_t)row*W + c];
        size_t idx2 = (size_t)row*W + c;
        if (out) out[idx2] = val2;
        __nv_bfloat16 hh2 = __float2bfloat16(val2);
        oh[idx2] = hh2;
        ol[idx2] = __float2bfloat16(val2 - __bfloat162float(hh2));
    }
}

// ---------------- Q/K/V -> bf16 hi/lo (Q pre-scaled by 1/sqrt(128)) ----------------
__global__ __launch_bounds__(256) void k_cvtqk(const float* __restrict__ qkv,
                                               __nv_bfloat16* __restrict__ qh,
                                               __nv_bfloat16* __restrict__ ql,
                                               __nv_bfloat16* __restrict__ kh,
                                               __nv_bfloat16* __restrict__ kl) {
    const float scale = 0.08838834764831845f;
    int idx = blockIdx.x*256 + threadIdx.x;
    int n = idx >> 10, c = idx & 1023;
    float v = qkv[(size_t)n*1536 + c];
    if (c < 512) v *= scale;
    __nv_bfloat16 h = __float2bfloat16(v);
    __nv_bfloat16 l = __float2bfloat16(v - __bfloat162float(h));
    int hd = c & 511;
    size_t o = (size_t)(hd >> 7)*N_NODES*128 + (size_t)n*128 + (hd & 127);
    if (c < 512) { qh[o] = h; ql[o] = l; }
    else         { kh[o] = h; kl[o] = l; }
}

__global__ __launch_bounds__(256) void k_cvtv(const float* __restrict__ qkv,
                                              __nv_bfloat16* __restrict__ vh,
                                              __nv_bfloat16* __restrict__ vl) {
    __shared__ float tile[32][33];
    int nt = blockIdx.x*32, dt = blockIdx.y*32;
    int tx = threadIdx.x & 31, ty = threadIdx.x >> 5;
    #pragma unroll
    for (int i = 0; i < 4; i++)
        tile[ty + i*8][tx] = qkv[(size_t)(nt + ty + i*8)*1536 + 1024 + dt + tx];
    __syncthreads();
    #pragma unroll
    for (int i = 0; i < 4; i++) {
        int d = dt + ty + i*8;
        float v = tile[tx][ty + i*8];
        __nv_bfloat16 h = __float2bfloat16(v);
        __nv_bfloat16 l = __float2bfloat16(v - __bfloat162float(h));
        size_t o = (size_t)d*N_NODES + nt + tx;
        vh[o] = h; vl[o] = l;
    }
}

// ---------------- flash attention: FA2-style register-resident S/P ----------------
// BQ=128 (8 warps x 16 q-rows), BKV=64, occ 1, K/V double-buffered via cp.async.
// smem: QH/QL (32KB each) + per-buffer {KH,KL,VH,VL} 16KB each x 2 buffers.
#define FL_QH 0
#define FL_QL 32768
#define FL_KV 65536           // + buf*65536; inside: KH 0, KL 16384, VH 32768, VL 49152
#define FL_TOTAL 196608

__device__ __forceinline__ uint32_t sofQb(int row, int g) {   // 128-col rows (256B)
    return (uint32_t)(row*256 + ((g ^ (row & 7)) << 4));
}
__device__ __forceinline__ uint32_t sofVb(int row, int g) {   // 64-col rows (128B)
    return (uint32_t)(row*128 + ((g ^ (row & 7)) << 4));
}

__global__ __launch_bounds__(256, 1) void k_flash(
    const __nv_bfloat16* __restrict__ qh, const __nv_bfloat16* __restrict__ ql,
    const __nv_bfloat16* __restrict__ kh, const __nv_bfloat16* __restrict__ kl,
    const __nv_bfloat16* __restrict__ vh, const __nv_bfloat16* __restrict__ vl,
    __nv_bfloat16* __restrict__ atth, __nv_bfloat16* __restrict__ attl)
{
    extern __shared__ char smf[];
    int qb = blockIdx.x, head = blockIdx.y, t = threadIdx.x;
    int w = t >> 5, lane = t & 31;
    int n0 = qb*128, coff = head*128;

    uint32_t qhB = s2u(smf + FL_QH), qlB = s2u(smf + FL_QL);

    // ---- load Q (static stores; ordered by first loop-top sync) ----
    const __nv_bfloat16* qhg = qh + ((size_t)head*N_NODES + n0)*128;
    const __nv_bfloat16* qlg = ql + ((size_t)head*N_NODES + n0)*128;
    #pragma unroll
    for (int l = 0; l < 8; l++) {
        int gid = t + l*256;
        int row = gid >> 4, g = gid & 15;
        uint32_t off = sofQb(row, g);
        *(uint4*)(smf + FL_QH + off) = *(const uint4*)(qhg + (size_t)row*128 + g*8);
        *(uint4*)(smf + FL_QL + off) = *(const uint4*)(qlg + (size_t)row*128 + g*8);
    }

    const __nv_bfloat16* khg = kh + (size_t)head*N_NODES*128;
    const __nv_bfloat16* klg = kl + (size_t)head*N_NODES*128;
    const __nv_bfloat16* vhg = vh + (size_t)head*128*N_NODES;
    const __nv_bfloat16* vlg = vl + (size_t)head*128*N_NODES;

    auto issue_kv = [&](int kb, int buf) {
        uint32_t base = s2u(smf + FL_KV) + buf*65536;
        #pragma unroll
        for (int l = 0; l < 4; l++) {
            int gid = t + l*256;
            int row = gid >> 4, g = gid & 15;
            uint32_t off = sofQb(row, g);
            size_t so = (size_t)(kb*64 + row)*128 + g*8;
            cpa16(base + off, khg + so, true);
            cpa16(base + 16384 + off, klg + so, true);
        }
        #pragma unroll
        for (int l = 0; l < 4; l++) {
            int gid = t + l*256;
            int row = gid >> 3, g = gid & 7;
            uint32_t off = sofVb(row, g);
            size_t so = (size_t)row*N_NODES + kb*64 + g*8;
            cpa16(base + 32768 + off, vhg + so, true);
            cpa16(base + 49152 + off, vlg + so, true);
        }
    };

    issue_kv(0, 0); CP_COMMIT();

    float oacc[16][4] = {};
    float m0 = -1e30f, m1 = -1e30f, l0 = 0.f, l1 = 0.f;

    int arow = w*16 + (lane & 15);
    int ag   = lane >> 4;
    int brow = ((lane >> 4) << 3) + (lane & 7);
    int bg   = (lane >> 3) & 1;

    for (int kb = 0; kb < 64; kb++) {
        __syncthreads();                       // all warps done with old buf
        if (kb + 1 < 64) issue_kv(kb + 1, (kb + 1) & 1);
        CP_COMMIT();
        CP_WAIT(1);                            // current buf complete
        __syncthreads();

        uint32_t base = s2u(smf + FL_KV) + (kb & 1)*65536;
        uint32_t khB = base, klB = base + 16384;
        uint32_t vhB = base + 32768, vlB = base + 49152;

        // ---- S = Q K^T : sacc[8] m16n8 frags (16 rows x 64 cols per warp) ----
        float sacc[8][4] = {};
        #pragma unroll
        for (int pass = 0; pass < 3; pass++) {
            uint32_t aB = (pass == 2) ? qlB : qhB;
            uint32_t bB = (pass == 1) ? klB : khB;
            #pragma unroll
            for (int ks = 0; ks < 8; ks++) {
                uint32_t afr[4], bfr[4][4];
                ldsm4(afr, aB + sofQb(arow, ag + ks*2));
                #pragma unroll
                for (int nb = 0; nb < 4; nb++)
                    ldsm4(bfr[nb], bB + sofQb(brow + nb*16, bg + ks*2));
                #pragma unroll
                for (int j = 0; j < 8; j++)
                    mma16816(sacc[j], afr, bfr[j >> 1][(j & 1)*2], bfr[j >> 1][(j & 1)*2 + 1]);
            }
        }

        // ---- register softmax (rows r0 = w*16 + lane>>2, r1 = r0+8) ----
        float mx0 = m0, mx1 = m1;
        #pragma unroll
        for (int j = 0; j < 8; j++) {
            mx0 = fmaxf(mx0, fmaxf(sacc[j][0], sacc[j][1]));
            mx1 = fmaxf(mx1, fmaxf(sacc[j][2], sacc[j][3]));
        }
        mx0 = fmaxf(mx0, __shfl_xor_sync(0xffffffffu, mx0, 1));
        mx0 = fmaxf(mx0, __shfl_xor_sync(0xffffffffu, mx0, 2));
        mx1 = fmaxf(mx1, __shfl_xor_sync(0xffffffffu, mx1, 1));
        mx1 = fmaxf(mx1, __shfl_xor_sync(0xffffffffu, mx1, 2));
        float f0 = __expf(m0 - mx0), f1 = __expf(m1 - mx1);
        float ls0 = 0.f, ls1 = 0.f;
        #pragma unroll
        for (int j = 0; j < 8; j++) {
            sacc[j][0] = __expf(sacc[j][0] - mx0);
            sacc[j][1] = __expf(sacc[j][1] - mx0);
            sacc[j][2] = __expf(sacc[j][2] - mx1);
            sacc[j][3] = __expf(sacc[j][3] - mx1);
            ls0 += sacc[j][0] + sacc[j][1];
            ls1 += sacc[j][2] + sacc[j][3];
        }
        ls0 += __shfl_xor_sync(0xffffffffu, ls0, 1);
        ls0 += __shfl_xor_sync(0xffffffffu, ls0, 2);
        ls1 += __shfl_xor_sync(0xffffffffu, ls1, 1);
        ls1 += __shfl_xor_sync(0xffffffffu, ls1, 2);
        l0 = l0*f0 + ls0;  m0 = mx0;
        l1 = l1*f1 + ls1;  m1 = mx1;

        // ---- rescale O ----
        #pragma unroll
        for (int nf = 0; nf < 16; nf++) {
            oacc[nf][0] *= f0; oacc[nf][1] *= f0;
            oacc[nf][2] *= f1; oacc[nf][3] *= f1;
        }

        // ---- P frags (in-register accum -> A mapping, hi/lo split) ----
        uint32_t ph[4][4], pl[4][4];
        #pragma unroll
        for (int ks = 0; ks < 4; ks++) {
            #pragma unroll
            for (int hq = 0; hq < 2; hq++) {        // hq: frag 2ks / 2ks+1
                const float* e = sacc[2*ks + hq];
                __nv_bfloat162 hA = __float22bfloat162_rn(make_float2(e[0], e[1]));
                __nv_bfloat162 hB = __float22bfloat162_rn(make_float2(e[2], e[3]));
                float2 fA = __bfloat1622float2(hA);
                float2 fB = __bfloat1622float2(hB);
                __nv_bfloat162 lA = __float22bfloat162_rn(make_float2(e[0]-fA.x, e[1]-fA.y));
                __nv_bfloat162 lB = __float22bfloat162_rn(make_float2(e[2]-fB.x, e[3]-fB.y));
                ph[ks][2*hq]     = b2u(hA);   // (r,  k cols)
                ph[ks][2*hq + 1] = b2u(hB);   // (r+8)
                pl[ks][2*hq]     = b2u(lA);
                pl[ks][2*hq + 1] = b2u(lB);
            }
            // reorder to a-frag: a0=(r,k0),a1=(r+8,k0),a2=(r,k8),a3=(r+8,k8)
            // built: [0]=(r,k0), [1]=(r+8,k0), [2]=(r,k8), [3]=(r+8,k8)  -> already correct
        }

        // ---- O += P V ----
        #pragma unroll
        for (int pass = 0; pass < 3; pass++) {
            uint32_t bB = (pass == 1) ? vlB : vhB;
            #pragma unroll
            for (int ks = 0; ks < 4; ks++) {
                const uint32_t (&A)[4] = (pass == 2) ? pl[ks] : ph[ks];
                uint32_t vfr[8][4];
                #pragma unroll
                for (int nb = 0; nb < 8; nb++)
                    ldsm4(vfr[nb], bB + sofVb(brow + nb*16, bg + ks*2));
                #pragma unroll
                for (int nf = 0; nf < 16; nf++)
                    mma16816(oacc[nf], A, vfr[nf >> 1][(nf & 1)*2], vfr[nf >> 1][(nf & 1)*2 + 1]);
            }
        }
    }

    // ---- epilogue ----
    int r = w*16 + (lane >> 2);
    float inv0 = 1.f / l0;
    float inv1 = 1.f / l1;
    #pragma unroll
    for (int nf = 0; nf < 16; nf++) {
        int col = coff + nf*8 + (lane & 3)*2;
        float a0 = oacc[nf][0]*inv0, a1 = oacc[nf][1]*inv0;
        float a2 = oacc[nf][2]*inv1, a3 = oacc[nf][3]*inv1;
        __nv_bfloat162 h01 = __float22bfloat162_rn(make_float2(a0, a1));
        float2 f01 = __bfloat1622float2(h01);
        __nv_bfloat162 l01 = __float22bfloat162_rn(make_float2(a0 - f01.x, a1 - f01.y));
        __nv_bfloat162 h23 = __float22bfloat162_rn(make_float2(a2, a3));
        float2 f23 = __bfloat1622float2(h23);
        __nv_bfloat162 l23 = __float22bfloat162_rn(make_float2(a2 - f23.x, a3 - f23.y));
        *(uint32_t*)&atth[(size_t)(n0 + r)*512 + col] = b2u(h01);
        *(uint32_t*)&attl[(size_t)(n0 + r)*512 + col] = b2u(l01);
        *(uint32_t*)&atth[(size_t)(n0 + r + 8)*512 + col] = b2u(h23);
        *(uint32_t*)&attl[(size_t)(n0 + r + 8)*512 + col] = b2u(l23);
    }
}

// ---------------- launch ----------------
extern "C" void kernel_launch(void* const* d_in, const int* in_sizes, int n_in,
                              void* d_out, int out_size) {
    const float* x          = (const float*)d_in[0];
    const int*   ei         = (const int*)  d_in[1];
    const float* sage_wl    = (const float*)d_in[2];
    const float* sage_wr    = (const float*)d_in[3];
    const float* sage_bl    = (const float*)d_in[4];
    const float* ln_g       = (const float*)d_in[5];
    const float* ln_b       = (const float*)d_in[6];
    const float* conv_w     = (const float*)d_in[7];
    const float* conv_b     = (const float*)d_in[8];
    const float* cnorm_g    = (const float*)d_in[9];
    const float* cnorm_b    = (const float*)d_in[10];
    const float* in_proj_w  = (const float*)d_in[11];
    const float* in_proj_b  = (const float*)d_in[12];
    const float* out_proj_w = (const float*)d_in[13];
    const float* out_proj_b = (const float*)d_in[14];
    const float* anorm_g    = (const float*)d_in[15];
    const float* anorm_b    = (const float*)d_in[16];
    const float* fuse_w     = (const float*)d_in[17];
    const float* fuse_b     = (const float*)d_in[18];
    float* outp = (float*)d_out;

    float *ph, *ptmp, *pqkv, *po;
    __nv_bfloat16 *paggh, *paggl, *phbh, *phbl, *pcah, *pcal, *pcbh, *pcbl;
    __nv_bfloat16 *patth, *pattl, *po2h, *po2l, *pwh, *pwl;
    __nv_bfloat16 *pqh, *pql, *pkh, *pkl, *pvh, *pvl;
    cudaGetSymbolAddress((void**)&ph,    g_h);
    cudaGetSymbolAddress((void**)&ptmp,  g_tmp);
    cudaGetSymbolAddress((void**)&pqkv,  g_qkv);
    cudaGetSymbolAddress((void**)&po,    g_o);
    cudaGetSymbolAddress((void**)&paggh, g_aggh);
    cudaGetSymbolAddress((void**)&paggl, g_aggl);
    cudaGetSymbolAddress((void**)&phbh,  g_hbh);
    cudaGetSymbolAddress((void**)&phbl,  g_hbl);
    cudaGetSymbolAddress((void**)&pcah,  g_cah);
    cudaGetSymbolAddress((void**)&pcal,  g_cal);
    cudaGetSymbolAddress((void**)&pcbh,  g_cbh);
    cudaGetSymbolAddress((void**)&pcbl,  g_cbl);
    cudaGetSymbolAddress((void**)&patth, g_atth);
    cudaGetSymbolAddress((void**)&pattl, g_attl);
    cudaGetSymbolAddress((void**)&po2h,  g_o2h);
    cudaGetSymbolAddress((void**)&po2l,  g_o2l);
    cudaGetSymbolAddress((void**)&pwh,   g_wh);
    cudaGetSymbolAddress((void**)&pwl,   g_wl);
    cudaGetSymbolAddress((void**)&pqh,   g_qh);
    cudaGetSymbolAddress((void**)&pql,   g_ql);
    cudaGetSymbolAddress((void**)&pkh,   g_kh);
    cudaGetSymbolAddress((void**)&pkl,   g_kl);
    cudaGetSymbolAddress((void**)&pvh,   g_vh);
    cudaGetSymbolAddress((void**)&pvl,   g_vl);

    cudaFuncSetAttribute(k_flash, cudaFuncAttributeMaxDynamicSharedMemorySize, FL_TOTAL);

    // CSR build + weight packing + x convert
    k_zero<<<16, 256>>>();
    k_count<<<E_EDGES/256, 256>>>(ei + E_EDGES);
    k_scan<<<1, 1024>>>();
    k_fill<<<E_EDGES/256, 256>>>(ei, ei + E_EDGES);
    k_packw<<<(1536*512+255)/256, 256>>>(sage_wl, sage_wr, sage_wl, 256, 1, 512,
                                         1536*512, pwh + W_SAGE, pwl + W_SAGE);
    k_packw<<<(768*768+255)/256, 256>>>(conv_w, conv_w + 1, conv_w + 2, 768, 3, 768,
                                        768*768, pwh + W_CONV, pwl + W_CONV);
    k_packw<<<(1536*512+255)/256, 256>>>(in_proj_w, in_proj_w + 256, in_proj_w, 512, 1, 512,
                                         1536*512, pwh + W_INP, pwl + W_INP);
    k_packw<<<(512*512+255)/256, 256>>>(out_proj_w, out_proj_w + 256, out_proj_w, 512, 1, 512,
                                        512*512, pwh + W_OUTP, pwl + W_OUTP);
    k_packw<<<(64*512+255)/256, 256>>>(fuse_w, fuse_w + 256, fuse_w, 512, 1, 512,
                                       64*512, pwh + W_FUSE, pwl + W_FUSE);
    k_cvtx<<<N_NODES*H/256, 256>>>(x, phbh, phbl);

    dim3 g_hh(4, 64);

    // ---- GNN: 6 SAGE layers ----
    const float* hcur = x;
    for (int i = 0; i < 6; i++) {
        k_agg<<<N_NODES, 256>>>(hcur, paggh, paggl);
        k_mma<<<g_hh, 128>>>(
            paggh, paggl, H, 0, phbh, phbl, H, 0, paggh, paggl, H, 0,
            pwh + W_SAGE + (size_t)i*H*512, pwl + W_SAGE + (size_t)i*H*512, 512,
            ptmp, H, N_NODES, 2*H, sage_bl + i*H);
        int flags = (i < 5) ? (F_LN | F_POSTRELU | F_RES) : (F_POSTRELU | F_RES);
        k_ln<<<N_NODES, 256>>>(ptmp, (i < 5) ? ln_g + i*H : nullptr,
                               (i < 5) ? ln_b + i*H : nullptr,
                               hcur, ph, phbh, phbl, H, flags);
        hcur = ph;
    }

    // ---- CNN branch ----
    __nv_bfloat16 *cinh = phbh, *cinl = phbl;
    __nv_bfloat16* ch[3] = {pcah, pcbh, pcah};
    __nv_bfloat16* cl[3] = {pcal, pcbl, pcal};
    for (int j = 0; j < 3; j++) {
        k_mma<<<g_hh, 128>>>(
            cinh, cinl, H, -1, cinh, cinl, H, 0, cinh, cinl, H, 1,
            pwh + W_CONV + (size_t)j*H*768, pwl + W_CONV + (size_t)j*H*768, 768,
            ptmp, H, N_NODES, 3*H, conv_b + j*H);
        k_ln<<<N_NODES, 256>>>(ptmp, cnorm_g + j*H, cnorm_b + j*H,
                               nullptr, nullptr, ch[j], cl[j], H, F_LN | F_PRERELU);
        cinh = ch[j]; cinl = cl[j];
    }

    // ---- qkv projection ----
    dim3 g_qkvd(24, 64);
    k_mma<<<g_qkvd, 128>>>(
        phbh, phbl, H, 0, cinh, cinl, H, 0, phbh, phbl, H, 0,
        pwh + W_INP, pwl + W_INP, 512,
        pqkv, 1536, N_NODES, 512, in_proj_b);

    // ---- convert Q/K/V ----
    k_cvtqk<<<(N_NODES*1024)/256, 256>>>(pqkv, pqh, pql, pkh, pkl);
    dim3 g_cv(N_NODES/32, 16);
    k_cvtv<<<g_cv, 256>>>(pqkv, pvh, pvl);

    // ---- flash attention ----
    dim3 g_fl(32, 4);
    k_flash<<<g_fl, 256, FL_TOTAL>>>(pqh, pql, pkh, pkl, pvh, pvl, patth, pattl);

    // ---- out_proj + LN + fuse ----
    dim3 g_op(8, 64);
    k_mma<<<g_op, 128>>>(
        patth, pattl, 512, 0, patth + 256, pattl + 256, 512, 0, patth, pattl, 512, 0,
        pwh + W_OUTP, pwl + W_OUTP, 512,
        po, 512, N_NODES, 512, out_proj_b);
    k_ln<<<N_NODES, 256>>>(po, anorm_g, anorm_b, nullptr, nullptr, po2h, po2l, 512, F_LN);
    dim3 g_fu(1, 64);
    k_mma<<<g_fu, 128>>>(
        po2h, po2l, 512, 0, po2h + 256, po2l + 256, 512, 0, po2h, po2l, 512, 0,
        pwh + W_FUSE, pwl + W_FUSE, 512,
        outp, 64, N_NODES, 512, fuse_b);
}